// round 1
// baseline (speedup 1.0000x reference)
#include <cuda_runtime.h>
#include <math.h>

// ---------------- constants ----------------
namespace {
constexpr int B_ = 8, S_ = 1024, D_ = 768, H_ = 12, DH_ = 64, L_ = 8, V_ = 1024;
constexpr int COND_ = 256, NACT_ = 4, DPA_ = 64;
constexpr int BS_ = B_ * S_;               // 8192
}

// ---------------- scratch (static device globals; no runtime alloc) ----------------
__device__ float g_x [BS_ * D_];
__device__ float g_h [BS_ * D_];
__device__ float g_q [BS_ * D_];           // layout [B,H,S,DH]
__device__ float g_k [BS_ * D_];
__device__ float g_v [BS_ * D_];
__device__ float g_o [BS_ * D_];           // layout [B,S,D]
__device__ float g_ff[BS_ * 4 * D_];
__device__ float g_a [B_ * COND_];
__device__ float g_gv[B_ * D_];
__device__ float g_bv[B_ * D_];

// ---------------- helpers ----------------
__device__ __forceinline__ float gelu_f(float x) {
    float x3 = x * x * x;
    return 0.5f * x * (1.f + tanhf(0.7978845608028654f * (x + 0.044715f * x3)));
}

// ---------------- embedding + sinusoidal PE ----------------
__global__ void k_embed(const int* __restrict__ tokens, const float* __restrict__ emb) {
    int row = blockIdx.x;                 // b*S + s
    int s = row & (S_ - 1);
    int tok = tokens[row];
    for (int d = threadIdx.x; d < D_; d += blockDim.x) {
        int p2 = d & ~1;                  // 2p
        float freq = expf(-(float)p2 * (9.210340371976184f / (float)D_));
        float ang = (float)s * freq;
        float pe = (d & 1) ? cosf(ang) : sinf(ang);
        g_x[row * D_ + d] = emb[tok * D_ + d] + pe;
    }
}

// ---------------- action embedding gather ----------------
__global__ void k_act(const int* __restrict__ actions, const float* __restrict__ act_emb) {
    int i = blockIdx.x * blockDim.x + threadIdx.x;
    if (i >= B_ * COND_) return;
    int b = i / COND_, c = i % COND_;
    int n = c / DPA_, j = c % DPA_;
    g_a[i] = act_emb[actions[b * NACT_ + n] * DPA_ + j];
}

// ---------------- conditional gain/shift vectors: g = a @ gw, b = a @ bw ----------------
__global__ void k_condvec(const float* __restrict__ gw, const float* __restrict__ bw) {
    int i = blockIdx.x * blockDim.x + threadIdx.x;
    if (i >= B_ * D_) return;
    int b = i / D_, d = i % D_;
    const float* ar = g_a + b * COND_;
    float sg = 0.f, sb = 0.f;
    for (int c = 0; c < COND_; c++) {
        float av = ar[c];
        sg += av * gw[c * D_ + d];
        sb += av * bw[c * D_ + d];
    }
    g_gv[i] = sg;
    g_bv[i] = sb;
}

// ---------------- conditional layernorm: g_x -> g_h ----------------
__global__ __launch_bounds__(256) void k_condln() {
    int row = blockIdx.x;
    int b = row >> 10;                    // row / S
    const float* xp = g_x + row * D_;
    int t = threadIdx.x;
    float x0 = xp[t], x1 = xp[t + 256], x2 = xp[t + 512];
    float s1 = x0 + x1 + x2;
    float s2 = x0 * x0 + x1 * x1 + x2 * x2;
    #pragma unroll
    for (int o = 16; o; o >>= 1) {
        s1 += __shfl_xor_sync(0xffffffffu, s1, o);
        s2 += __shfl_xor_sync(0xffffffffu, s2, o);
    }
    __shared__ float rs1[8], rs2[8];
    __shared__ float mu_s, rstd_s;
    int w = t >> 5;
    if ((t & 31) == 0) { rs1[w] = s1; rs2[w] = s2; }
    __syncthreads();
    if (t == 0) {
        float a1 = 0.f, a2 = 0.f;
        #pragma unroll
        for (int i = 0; i < 8; i++) { a1 += rs1[i]; a2 += rs2[i]; }
        float mu = a1 / (float)D_;
        float var = a2 / (float)D_ - mu * mu;
        mu_s = mu;
        rstd_s = rsqrtf(var + 1e-5f);
    }
    __syncthreads();
    float mu = mu_s, rstd = rstd_s;
    const float* gv = g_gv + b * D_;
    const float* bv = g_bv + b * D_;
    float* hp = g_h + row * D_;
    hp[t]       = (x0 - mu) * rstd * gv[t]       + bv[t];
    hp[t + 256] = (x1 - mu) * rstd * gv[t + 256] + bv[t + 256];
    hp[t + 512] = (x2 - mu) * rstd * gv[t + 512] + bv[t + 512];
}

// ---------------- per-head QKV projection: g_h -> g_q/g_k/g_v ([B,H,S,DH]) ----------------
__global__ __launch_bounds__(256) void k_qkv(const float* __restrict__ wq,
                                             const float* __restrict__ wk,
                                             const float* __restrict__ wv) {
    __shared__ float Xs[64][65];
    __shared__ float Ws[64][65];
    int rowBase = blockIdx.x * 64;        // over B*S
    int h = blockIdx.y;
    int t = threadIdx.x;
    // load X tile (64 rows x this head's 64 cols)
    #pragma unroll
    for (int u = 0; u < 16; u++) {
        int idx = t + u * 256;
        int i = idx >> 6, d = idx & 63;
        Xs[i][d] = g_h[(rowBase + i) * D_ + h * DH_ + d];
    }
    int r = t >> 2, g = t & 3;
    const float* ws[3] = { wq + h * DH_ * DH_, wk + h * DH_ * DH_, wv + h * DH_ * DH_ };
    float* outs[3] = { g_q, g_k, g_v };
    int gr = rowBase + r;
    int b = gr >> 10, s = gr & (S_ - 1);
    for (int w3 = 0; w3 < 3; w3++) {
        __syncthreads();
        #pragma unroll
        for (int u = 0; u < 16; u++) {
            int idx = t + u * 256;
            int d = idx >> 6, e = idx & 63;
            Ws[d][e] = ws[w3][d * DH_ + e];
        }
        __syncthreads();
        float acc[16];
        #pragma unroll
        for (int e = 0; e < 16; e++) acc[e] = 0.f;
        for (int d = 0; d < 64; d++) {
            float xv = Xs[r][d];
            #pragma unroll
            for (int e = 0; e < 16; e++) acc[e] += xv * Ws[d][g * 16 + e];
        }
        float* outp = outs[w3] + ((b * H_ + h) * S_ + s) * DH_ + g * 16;
        #pragma unroll
        for (int e = 0; e < 16; e++) outp[e] = acc[e];
    }
}

// ---------------- flash attention (non-causal, full softmax), q/k/v [B,H,S,DH] -> g_o [B,S,D] ----------------
__global__ __launch_bounds__(256) void k_flash() {
    extern __shared__ float sm[];
    float* Qs = sm;                       // 64*65
    float* Ks = Qs + 64 * 65;
    float* Vs = Ks + 64 * 65;
    float* Ps = Vs + 64 * 65;
    int bh = blockIdx.y;
    int qBase = blockIdx.x * 64;
    int t = threadIdx.x;
    int r = t >> 2, g = t & 3;
    const float* qp = g_q + (bh * S_ + qBase) * DH_;
    #pragma unroll
    for (int u = 0; u < 16; u++) {
        int idx = t + u * 256;
        int i = idx >> 6, d = idx & 63;
        Qs[i * 65 + d] = qp[i * DH_ + d] * 0.125f;   // 1/sqrt(64)
    }
    float m = -1e30f, l = 0.f;
    float acc[16];
    #pragma unroll
    for (int c = 0; c < 16; c++) acc[c] = 0.f;

    for (int kt = 0; kt < S_; kt += 64) {
        const float* kp = g_k + (bh * S_ + kt) * DH_;
        const float* vp = g_v + (bh * S_ + kt) * DH_;
        __syncthreads();                  // prev O-phase done before overwriting Ks/Vs
        #pragma unroll
        for (int u = 0; u < 16; u++) {
            int idx = t + u * 256;
            int i = idx >> 6, d = idx & 63;
            Ks[i * 65 + d] = kp[i * DH_ + d];
            Vs[i * 65 + d] = vp[i * DH_ + d];
        }
        __syncthreads();
        // scores for my 16 columns
        float sv[16];
        #pragma unroll
        for (int jj = 0; jj < 16; jj++) sv[jj] = 0.f;
        for (int d = 0; d < 64; d++) {
            float qd = Qs[r * 65 + d];
            #pragma unroll
            for (int jj = 0; jj < 16; jj++)
                sv[jj] += qd * Ks[(g * 16 + jj) * 65 + d];
        }
        float tmax = sv[0];
        #pragma unroll
        for (int jj = 1; jj < 16; jj++) tmax = fmaxf(tmax, sv[jj]);
        tmax = fmaxf(tmax, __shfl_xor_sync(0xffffffffu, tmax, 1));
        tmax = fmaxf(tmax, __shfl_xor_sync(0xffffffffu, tmax, 2));
        float mnew = fmaxf(m, tmax);
        float corr = expf(m - mnew);
        float psum = 0.f;
        #pragma unroll
        for (int jj = 0; jj < 16; jj++) {
            float p = expf(sv[jj] - mnew);
            psum += p;
            Ps[r * 65 + g * 16 + jj] = p;
        }
        psum += __shfl_xor_sync(0xffffffffu, psum, 1);
        psum += __shfl_xor_sync(0xffffffffu, psum, 2);
        l = l * corr + psum;
        m = mnew;
        #pragma unroll
        for (int c = 0; c < 16; c++) acc[c] *= corr;
        __syncthreads();                  // Ps fully written
        for (int j = 0; j < 64; j++) {
            float pv = Ps[r * 65 + j];
            #pragma unroll
            for (int cc = 0; cc < 16; cc++)
                acc[cc] += pv * Vs[j * 65 + g * 16 + cc];
        }
    }
    float inv = 1.f / l;
    int b = bh / H_, hh = bh % H_;
    float* outp = g_o + (b * S_ + qBase + r) * D_ + hh * DH_ + g * 16;
    #pragma unroll
    for (int cc = 0; cc < 16; cc++) outp[cc] = acc[cc] * inv;
}

// ---------------- 128x128x8 fp32 SGEMM, fused bias / gelu / residual epilogue ----------------
// C[M,N] = epi(A[M,K] @ W[K,N] + bias[N]);  epi: 0=none, 1=gelu, 2=+res[M,N]
__global__ __launch_bounds__(256) void k_gemm(const float* __restrict__ A,
                                              const float* __restrict__ W,
                                              const float* __restrict__ bias,
                                              const float* __restrict__ res,
                                              float* __restrict__ C,
                                              int M, int N, int K, int epi) {
    __shared__ float As[8][128];
    __shared__ float Bs[8][128];
    int t = threadIdx.x;
    int rowBase = blockIdx.y * 128;
    int colBase = blockIdx.x * 128;
    int tx = t & 15, ty = t >> 4;
    float acc[8][8];
    #pragma unroll
    for (int i = 0; i < 8; i++)
        #pragma unroll
        for (int j = 0; j < 8; j++) acc[i][j] = 0.f;

    int aRow = t >> 1, aCol = (t & 1) * 4;
    int bRow = t >> 5, bCol = (t & 31) * 4;
    const float* Ap = A + (rowBase + aRow) * K + aCol;
    const float* Wp = W + bRow * N + colBase + bCol;

    for (int kt = 0; kt < K; kt += 8) {
        float4 av = *(const float4*)(Ap + kt);
        float4 bv = *(const float4*)(Wp + kt * N);
        As[aCol + 0][aRow] = av.x;
        As[aCol + 1][aRow] = av.y;
        As[aCol + 2][aRow] = av.z;
        As[aCol + 3][aRow] = av.w;
        *(float4*)&Bs[bRow][bCol] = bv;
        __syncthreads();
        #pragma unroll
        for (int kk = 0; kk < 8; kk++) {
            float4 a0 = *(const float4*)&As[kk][ty * 8];
            float4 a1 = *(const float4*)&As[kk][ty * 8 + 4];
            float4 b0 = *(const float4*)&Bs[kk][tx * 8];
            float4 b1 = *(const float4*)&Bs[kk][tx * 8 + 4];
            float af[8] = { a0.x, a0.y, a0.z, a0.w, a1.x, a1.y, a1.z, a1.w };
            float bf[8] = { b0.x, b0.y, b0.z, b0.w, b1.x, b1.y, b1.z, b1.w };
            #pragma unroll
            for (int i = 0; i < 8; i++)
                #pragma unroll
                for (int j = 0; j < 8; j++) acc[i][j] += af[i] * bf[j];
        }
        __syncthreads();
    }
    #pragma unroll
    for (int i = 0; i < 8; i++) {
        int row = rowBase + ty * 8 + i;
        #pragma unroll
        for (int j = 0; j < 8; j++) {
            int col = colBase + tx * 8 + j;
            float v = acc[i][j] + bias[col];
            if (epi == 1) v = gelu_f(v);
            else if (epi == 2) v += res[row * N + col];
            C[row * N + col] = v;
        }
    }
}

// ---------------- launch sequence ----------------
extern "C" void kernel_launch(void* const* d_in, const int* in_sizes, int n_in,
                              void* d_out, int out_size) {
    const int*   tokens  = (const int*)d_in[0];
    const int*   actions = (const int*)d_in[1];
    const float* emb     = (const float*)d_in[2];
    const float* act_emb = (const float*)d_in[3];
    const float* ln1_g   = (const float*)d_in[4];
    const float* ln1_b   = (const float*)d_in[5];
    const float* Wq      = (const float*)d_in[6];
    const float* Wk      = (const float*)d_in[7];
    const float* Wv      = (const float*)d_in[8];
    const float* Wo      = (const float*)d_in[9];
    const float* bo      = (const float*)d_in[10];
    const float* ln2_g   = (const float*)d_in[11];
    const float* ln2_b   = (const float*)d_in[12];
    const float* W1      = (const float*)d_in[13];
    const float* b1      = (const float*)d_in[14];
    const float* W2      = (const float*)d_in[15];
    const float* b2      = (const float*)d_in[16];
    const float* lnf_g   = (const float*)d_in[17];
    const float* lnf_b   = (const float*)d_in[18];
    const float* Wout    = (const float*)d_in[19];
    const float* bout    = (const float*)d_in[20];

    float *xp, *hp, *op, *ffp;
    cudaGetSymbolAddress((void**)&xp,  g_x);
    cudaGetSymbolAddress((void**)&hp,  g_h);
    cudaGetSymbolAddress((void**)&op,  g_o);
    cudaGetSymbolAddress((void**)&ffp, g_ff);

    const int flashSmem = 4 * 64 * 65 * (int)sizeof(float);   // 66560 B
    cudaFuncSetAttribute(k_flash, cudaFuncAttributeMaxDynamicSharedMemorySize, flashSmem);

    k_embed<<<BS_, 256>>>(tokens, emb);
    k_act<<<(B_ * COND_ + 255) / 256, 256>>>(actions, act_emb);

    for (int l = 0; l < L_; l++) {
        size_t lnOff = (size_t)l * COND_ * D_;
        k_condvec<<<(B_ * D_ + 255) / 256, 256>>>(ln1_g + lnOff, ln1_b + lnOff);
        k_condln<<<BS_, 256>>>();
        k_qkv<<<dim3(BS_ / 64, H_), 256>>>(Wq + (size_t)l * H_ * DH_ * DH_,
                                           Wk + (size_t)l * H_ * DH_ * DH_,
                                           Wv + (size_t)l * H_ * DH_ * DH_);
        k_flash<<<dim3(S_ / 64, B_ * H_), 256, flashSmem>>>();
        // x = x + o @ Wo + bo
        k_gemm<<<dim3(D_ / 128, BS_ / 128), 256>>>(op, Wo + (size_t)l * D_ * D_,
                                                   bo + l * D_, xp, xp,
                                                   BS_, D_, D_, 2);
        k_condvec<<<(B_ * D_ + 255) / 256, 256>>>(ln2_g + lnOff, ln2_b + lnOff);
        k_condln<<<BS_, 256>>>();
        // ff = gelu(h @ W1 + b1)
        k_gemm<<<dim3(4 * D_ / 128, BS_ / 128), 256>>>(hp, W1 + (size_t)l * D_ * 4 * D_,
                                                       b1 + l * 4 * D_, nullptr, ffp,
                                                       BS_, 4 * D_, D_, 1);
        // x = x + ff @ W2 + b2
        k_gemm<<<dim3(D_ / 128, BS_ / 128), 256>>>(ffp, W2 + (size_t)l * 4 * D_ * D_,
                                                   b2 + l * D_, xp, xp,
                                                   BS_, D_, 4 * D_, 2);
    }
    k_condvec<<<(B_ * D_ + 255) / 256, 256>>>(lnf_g, lnf_b);
    k_condln<<<BS_, 256>>>();
    // out = h @ Wout + bout
    k_gemm<<<dim3(V_ / 128, BS_ / 128), 256>>>(hp, Wout, bout, nullptr,
                                               (float*)d_out, BS_, V_, D_, 0);
}

// round 2
// speedup vs baseline: 1.1739x; 1.1739x over previous
#include <cuda_runtime.h>
#include <math.h>
#include <mma.h>

using namespace nvcuda;

// ---------------- constants ----------------
namespace {
constexpr int B_ = 8, S_ = 1024, D_ = 768, H_ = 12, DH_ = 64, L_ = 8, V_ = 1024;
constexpr int COND_ = 256, NACT_ = 4, DPA_ = 64;
constexpr int BS_ = B_ * S_;               // 8192
// GEMM tiling
constexpr int BM = 128, BN = 128, BK = 32;
constexpr int LDA_S = 36;                  // padded smem leading dims (multiple of 4 floats)
constexpr int LDB_S = 132;
constexpr int LDC_S = 132;
}

// ---------------- scratch (static device globals; no runtime alloc) ----------------
__device__ float g_x [BS_ * D_];
__device__ float g_h [BS_ * D_];
__device__ float g_q [BS_ * D_];           // layout [B,H,S,DH]
__device__ float g_k [BS_ * D_];
__device__ float g_v [BS_ * D_];
__device__ float g_o [BS_ * D_];           // layout [B,S,D]
__device__ float g_ff[BS_ * 4 * D_];
__device__ float g_a [B_ * COND_];
__device__ float g_gv[B_ * D_];
__device__ float g_bv[B_ * D_];

// ---------------- helpers ----------------
__device__ __forceinline__ float gelu_f(float x) {
    float x3 = x * x * x;
    return 0.5f * x * (1.f + tanhf(0.7978845608028654f * (x + 0.044715f * x3)));
}

// ---------------- embedding + sinusoidal PE ----------------
__global__ void k_embed(const int* __restrict__ tokens, const float* __restrict__ emb) {
    int row = blockIdx.x;                 // b*S + s
    int s = row & (S_ - 1);
    int tok = tokens[row];
    for (int d = threadIdx.x; d < D_; d += blockDim.x) {
        int p2 = d & ~1;                  // 2p
        float freq = expf(-(float)p2 * (9.210340371976184f / (float)D_));
        float ang = (float)s * freq;
        float pe = (d & 1) ? cosf(ang) : sinf(ang);
        g_x[row * D_ + d] = emb[tok * D_ + d] + pe;
    }
}

// ---------------- action embedding gather ----------------
__global__ void k_act(const int* __restrict__ actions, const float* __restrict__ act_emb) {
    int i = blockIdx.x * blockDim.x + threadIdx.x;
    if (i >= B_ * COND_) return;
    int b = i / COND_, c = i % COND_;
    int n = c / DPA_, j = c % DPA_;
    g_a[i] = act_emb[actions[b * NACT_ + n] * DPA_ + j];
}

// ---------------- conditional gain/shift vectors: g = a @ gw, b = a @ bw ----------------
__global__ void k_condvec(const float* __restrict__ gw, const float* __restrict__ bw) {
    int i = blockIdx.x * blockDim.x + threadIdx.x;
    if (i >= B_ * D_) return;
    int b = i / D_, d = i % D_;
    const float* ar = g_a + b * COND_;
    float sg = 0.f, sb = 0.f;
    for (int c = 0; c < COND_; c++) {
        float av = ar[c];
        sg += av * gw[c * D_ + d];
        sb += av * bw[c * D_ + d];
    }
    g_gv[i] = sg;
    g_bv[i] = sb;
}

// ---------------- conditional layernorm: g_x -> g_h ----------------
__global__ __launch_bounds__(256) void k_condln() {
    int row = blockIdx.x;
    int b = row >> 10;                    // row / S
    const float* xp = g_x + row * D_;
    int t = threadIdx.x;
    float x0 = xp[t], x1 = xp[t + 256], x2 = xp[t + 512];
    float s1 = x0 + x1 + x2;
    float s2 = x0 * x0 + x1 * x1 + x2 * x2;
    #pragma unroll
    for (int o = 16; o; o >>= 1) {
        s1 += __shfl_xor_sync(0xffffffffu, s1, o);
        s2 += __shfl_xor_sync(0xffffffffu, s2, o);
    }
    __shared__ float rs1[8], rs2[8];
    __shared__ float mu_s, rstd_s;
    int w = t >> 5;
    if ((t & 31) == 0) { rs1[w] = s1; rs2[w] = s2; }
    __syncthreads();
    if (t == 0) {
        float a1 = 0.f, a2 = 0.f;
        #pragma unroll
        for (int i = 0; i < 8; i++) { a1 += rs1[i]; a2 += rs2[i]; }
        float mu = a1 / (float)D_;
        float var = a2 / (float)D_ - mu * mu;
        mu_s = mu;
        rstd_s = rsqrtf(var + 1e-5f);
    }
    __syncthreads();
    float mu = mu_s, rstd = rstd_s;
    const float* gv = g_gv + b * D_;
    const float* bv = g_bv + b * D_;
    float* hp = g_h + row * D_;
    hp[t]       = (x0 - mu) * rstd * gv[t]       + bv[t];
    hp[t + 256] = (x1 - mu) * rstd * gv[t + 256] + bv[t + 256];
    hp[t + 512] = (x2 - mu) * rstd * gv[t + 512] + bv[t + 512];
}

// ---------------- per-head QKV projection: g_h -> g_q/g_k/g_v ([B,H,S,DH]) ----------------
__global__ __launch_bounds__(256) void k_qkv(const float* __restrict__ wq,
                                             const float* __restrict__ wk,
                                             const float* __restrict__ wv) {
    __shared__ float Xs[64][65];
    __shared__ float Ws[64][65];
    int rowBase = blockIdx.x * 64;        // over B*S
    int h = blockIdx.y;
    int t = threadIdx.x;
    // load X tile (64 rows x this head's 64 cols)
    #pragma unroll
    for (int u = 0; u < 16; u++) {
        int idx = t + u * 256;
        int i = idx >> 6, d = idx & 63;
        Xs[i][d] = g_h[(rowBase + i) * D_ + h * DH_ + d];
    }
    int r = t >> 2, g = t & 3;
    const float* ws[3] = { wq + h * DH_ * DH_, wk + h * DH_ * DH_, wv + h * DH_ * DH_ };
    float* outs[3] = { g_q, g_k, g_v };
    int gr = rowBase + r;
    int b = gr >> 10, s = gr & (S_ - 1);
    for (int w3 = 0; w3 < 3; w3++) {
        __syncthreads();
        #pragma unroll
        for (int u = 0; u < 16; u++) {
            int idx = t + u * 256;
            int d = idx >> 6, e = idx & 63;
            Ws[d][e] = ws[w3][d * DH_ + e];
        }
        __syncthreads();
        float acc[16];
        #pragma unroll
        for (int e = 0; e < 16; e++) acc[e] = 0.f;
        for (int d = 0; d < 64; d++) {
            float xv = Xs[r][d];
            #pragma unroll
            for (int e = 0; e < 16; e++) acc[e] += xv * Ws[d][g * 16 + e];
        }
        float* outp = outs[w3] + ((b * H_ + h) * S_ + s) * DH_ + g * 16;
        #pragma unroll
        for (int e = 0; e < 16; e++) outp[e] = acc[e];
    }
}

// ---------------- flash attention (non-causal, full softmax), q/k/v [B,H,S,DH] -> g_o [B,S,D] ----------------
__global__ __launch_bounds__(256) void k_flash() {
    extern __shared__ float sm[];
    float* Qs = sm;                       // 64*65
    float* Ks = Qs + 64 * 65;
    float* Vs = Ks + 64 * 65;
    float* Ps = Vs + 64 * 65;
    int bh = blockIdx.y;
    int qBase = blockIdx.x * 64;
    int t = threadIdx.x;
    int r = t >> 2, g = t & 3;
    const float* qp = g_q + (bh * S_ + qBase) * DH_;
    #pragma unroll
    for (int u = 0; u < 16; u++) {
        int idx = t + u * 256;
        int i = idx >> 6, d = idx & 63;
        Qs[i * 65 + d] = qp[i * DH_ + d] * 0.125f;   // 1/sqrt(64)
    }
    float m = -1e30f, l = 0.f;
    float acc[16];
    #pragma unroll
    for (int c = 0; c < 16; c++) acc[c] = 0.f;

    for (int kt = 0; kt < S_; kt += 64) {
        const float* kp = g_k + (bh * S_ + kt) * DH_;
        const float* vp = g_v + (bh * S_ + kt) * DH_;
        __syncthreads();                  // prev O-phase done before overwriting Ks/Vs
        #pragma unroll
        for (int u = 0; u < 16; u++) {
            int idx = t + u * 256;
            int i = idx >> 6, d = idx & 63;
            Ks[i * 65 + d] = kp[i * DH_ + d];
            Vs[i * 65 + d] = vp[i * DH_ + d];
        }
        __syncthreads();
        // scores for my 16 columns
        float sv[16];
        #pragma unroll
        for (int jj = 0; jj < 16; jj++) sv[jj] = 0.f;
        for (int d = 0; d < 64; d++) {
            float qd = Qs[r * 65 + d];
            #pragma unroll
            for (int jj = 0; jj < 16; jj++)
                sv[jj] += qd * Ks[(g * 16 + jj) * 65 + d];
        }
        float tmax = sv[0];
        #pragma unroll
        for (int jj = 1; jj < 16; jj++) tmax = fmaxf(tmax, sv[jj]);
        tmax = fmaxf(tmax, __shfl_xor_sync(0xffffffffu, tmax, 1));
        tmax = fmaxf(tmax, __shfl_xor_sync(0xffffffffu, tmax, 2));
        float mnew = fmaxf(m, tmax);
        float corr = expf(m - mnew);
        float psum = 0.f;
        #pragma unroll
        for (int jj = 0; jj < 16; jj++) {
            float p = expf(sv[jj] - mnew);
            psum += p;
            Ps[r * 65 + g * 16 + jj] = p;
        }
        psum += __shfl_xor_sync(0xffffffffu, psum, 1);
        psum += __shfl_xor_sync(0xffffffffu, psum, 2);
        l = l * corr + psum;
        m = mnew;
        #pragma unroll
        for (int c = 0; c < 16; c++) acc[c] *= corr;
        __syncthreads();                  // Ps fully written
        for (int j = 0; j < 64; j++) {
            float pv = Ps[r * 65 + j];
            #pragma unroll
            for (int cc = 0; cc < 16; cc++)
                acc[cc] += pv * Vs[j * 65 + g * 16 + cc];
        }
    }
    float inv = 1.f / l;
    int b = bh / H_, hh = bh % H_;
    float* outp = g_o + (b * S_ + qBase + r) * D_ + hh * DH_ + g * 16;
    #pragma unroll
    for (int cc = 0; cc < 16; cc++) outp[cc] = acc[cc] * inv;
}

// ---------------- TF32 tensor-core GEMM, 128x128x32 tile, fused epilogue ----------------
// C[M,N] = epi(A[M,K] @ W[K,N] + bias[N]);  epi: 0=none, 1=gelu, 2=+res[M,N]
// 8 warps arranged 2(M) x 4(N); each warp computes 64x32 via 4x2 wmma m16n16k8 frags.
__global__ __launch_bounds__(256) void k_gemm_tc(const float* __restrict__ A,
                                                 const float* __restrict__ W,
                                                 const float* __restrict__ bias,
                                                 const float* __restrict__ res,
                                                 float* __restrict__ C,
                                                 int M, int N, int K, int epi) {
    extern __shared__ float smem[];
    float* As = smem;                 // [BM][LDA_S]
    float* Bs = smem + BM * LDA_S;    // [BK][LDB_S]
    float* Cs = smem;                 // [BM][LDC_S] (reused after k-loop)

    int t = threadIdx.x;
    int wid = t >> 5;
    int warpM = wid >> 2;             // 0..1
    int warpN = wid & 3;              // 0..3
    int rowBase = blockIdx.y * BM;
    int colBase = blockIdx.x * BN;

    wmma::fragment<wmma::accumulator, 16, 16, 8, float> cf[4][2];
    #pragma unroll
    for (int i = 0; i < 4; i++)
        #pragma unroll
        for (int j = 0; j < 2; j++) wmma::fill_fragment(cf[i][j], 0.f);

    int aRow = t >> 3, aCol = (t & 7) * 4;     // A: 32 rows/pass, 4 passes
    int bRow = t >> 5, bCol = (t & 31) * 4;    // B: 8 rows/pass, 4 passes

    for (int kt = 0; kt < K; kt += BK) {
        __syncthreads();
        #pragma unroll
        for (int p = 0; p < 4; p++) {
            int r = aRow + p * 32;
            float4 v = *(const float4*)(A + (size_t)(rowBase + r) * K + kt + aCol);
            *(float4*)&As[r * LDA_S + aCol] = v;
        }
        #pragma unroll
        for (int p = 0; p < 4; p++) {
            int r = bRow + p * 8;
            float4 v = *(const float4*)(W + (size_t)(kt + r) * N + colBase + bCol);
            *(float4*)&Bs[r * LDB_S + bCol] = v;
        }
        __syncthreads();
        #pragma unroll
        for (int kk = 0; kk < BK; kk += 8) {
            wmma::fragment<wmma::matrix_a, 16, 16, 8, wmma::precision::tf32, wmma::row_major> af[4];
            wmma::fragment<wmma::matrix_b, 16, 16, 8, wmma::precision::tf32, wmma::row_major> bf[2];
            #pragma unroll
            for (int i = 0; i < 4; i++) {
                wmma::load_matrix_sync(af[i], &As[(warpM * 64 + i * 16) * LDA_S + kk], LDA_S);
                #pragma unroll
                for (int e = 0; e < af[i].num_elements; e++)
                    af[i].x[e] = wmma::__float_to_tf32(af[i].x[e]);
            }
            #pragma unroll
            for (int j = 0; j < 2; j++) {
                wmma::load_matrix_sync(bf[j], &Bs[kk * LDB_S + warpN * 32 + j * 16], LDB_S);
                #pragma unroll
                for (int e = 0; e < bf[j].num_elements; e++)
                    bf[j].x[e] = wmma::__float_to_tf32(bf[j].x[e]);
            }
            #pragma unroll
            for (int i = 0; i < 4; i++)
                #pragma unroll
                for (int j = 0; j < 2; j++)
                    wmma::mma_sync(cf[i][j], af[i], bf[j], cf[i][j]);
        }
    }
    __syncthreads();  // k-loop reads done; safe to overwrite smem with C tile
    #pragma unroll
    for (int i = 0; i < 4; i++)
        #pragma unroll
        for (int j = 0; j < 2; j++)
            wmma::store_matrix_sync(&Cs[(warpM * 64 + i * 16) * LDC_S + warpN * 32 + j * 16],
                                    cf[i][j], LDC_S, wmma::mem_row_major);
    __syncthreads();

    // epilogue: 256 threads sweep 128x128, float4
    int cRow = t >> 5, cCol = (t & 31) * 4;
    #pragma unroll
    for (int p = 0; p < 16; p++) {
        int r = cRow + p * 8;
        int row = rowBase + r;
        int col = colBase + cCol;
        float4 v = *(float4*)&Cs[r * LDC_S + cCol];
        float4 bb = *(const float4*)(bias + col);
        v.x += bb.x; v.y += bb.y; v.z += bb.z; v.w += bb.w;
        if (epi == 1) {
            v.x = gelu_f(v.x); v.y = gelu_f(v.y); v.z = gelu_f(v.z); v.w = gelu_f(v.w);
        } else if (epi == 2) {
            float4 rr = *(const float4*)(res + (size_t)row * N + col);
            v.x += rr.x; v.y += rr.y; v.z += rr.z; v.w += rr.w;
        }
        *(float4*)(C + (size_t)row * N + col) = v;
    }
}

// ---------------- launch sequence ----------------
extern "C" void kernel_launch(void* const* d_in, const int* in_sizes, int n_in,
                              void* d_out, int out_size) {
    const int*   tokens  = (const int*)d_in[0];
    const int*   actions = (const int*)d_in[1];
    const float* emb     = (const float*)d_in[2];
    const float* act_emb = (const float*)d_in[3];
    const float* ln1_g   = (const float*)d_in[4];
    const float* ln1_b   = (const float*)d_in[5];
    const float* Wq      = (const float*)d_in[6];
    const float* Wk      = (const float*)d_in[7];
    const float* Wv      = (const float*)d_in[8];
    const float* Wo      = (const float*)d_in[9];
    const float* bo      = (const float*)d_in[10];
    const float* ln2_g   = (const float*)d_in[11];
    const float* ln2_b   = (const float*)d_in[12];
    const float* W1      = (const float*)d_in[13];
    const float* b1      = (const float*)d_in[14];
    const float* W2      = (const float*)d_in[15];
    const float* b2      = (const float*)d_in[16];
    const float* lnf_g   = (const float*)d_in[17];
    const float* lnf_b   = (const float*)d_in[18];
    const float* Wout    = (const float*)d_in[19];
    const float* bout    = (const float*)d_in[20];

    float *xp, *hp, *op, *ffp;
    cudaGetSymbolAddress((void**)&xp,  g_x);
    cudaGetSymbolAddress((void**)&hp,  g_h);
    cudaGetSymbolAddress((void**)&op,  g_o);
    cudaGetSymbolAddress((void**)&ffp, g_ff);

    const int flashSmem = 4 * 64 * 65 * (int)sizeof(float);   // 66560 B
    cudaFuncSetAttribute(k_flash, cudaFuncAttributeMaxDynamicSharedMemorySize, flashSmem);
    const int gemmSmem = BM * LDC_S * (int)sizeof(float);     // 67584 B (>= As+Bs)
    cudaFuncSetAttribute(k_gemm_tc, cudaFuncAttributeMaxDynamicSharedMemorySize, gemmSmem);

    k_embed<<<BS_, 256>>>(tokens, emb);
    k_act<<<(B_ * COND_ + 255) / 256, 256>>>(actions, act_emb);

    for (int l = 0; l < L_; l++) {
        size_t lnOff = (size_t)l * COND_ * D_;
        k_condvec<<<(B_ * D_ + 255) / 256, 256>>>(ln1_g + lnOff, ln1_b + lnOff);
        k_condln<<<BS_, 256>>>();
        k_qkv<<<dim3(BS_ / 64, H_), 256>>>(Wq + (size_t)l * H_ * DH_ * DH_,
                                           Wk + (size_t)l * H_ * DH_ * DH_,
                                           Wv + (size_t)l * H_ * DH_ * DH_);
        k_flash<<<dim3(S_ / 64, B_ * H_), 256, flashSmem>>>();
        // x = x + o @ Wo + bo
        k_gemm_tc<<<dim3(D_ / BN, BS_ / BM), 256, gemmSmem>>>(op, Wo + (size_t)l * D_ * D_,
                                                              bo + l * D_, xp, xp,
                                                              BS_, D_, D_, 2);
        k_condvec<<<(B_ * D_ + 255) / 256, 256>>>(ln2_g + lnOff, ln2_b + lnOff);
        k_condln<<<BS_, 256>>>();
        // ff = gelu(h @ W1 + b1)
        k_gemm_tc<<<dim3(4 * D_ / BN, BS_ / BM), 256, gemmSmem>>>(hp, W1 + (size_t)l * D_ * 4 * D_,
                                                                  b1 + l * 4 * D_, nullptr, ffp,
                                                                  BS_, 4 * D_, D_, 1);
        // x = x + ff @ W2 + b2
        k_gemm_tc<<<dim3(D_ / BN, BS_ / BM), 256, gemmSmem>>>(ffp, W2 + (size_t)l * 4 * D_ * D_,
                                                              b2 + l * D_, xp, xp,
                                                              BS_, D_, 4 * D_, 2);
    }
    k_condvec<<<(B_ * D_ + 255) / 256, 256>>>(lnf_g, lnf_b);
    k_condln<<<BS_, 256>>>();
    // out = h @ Wout + bout
    k_gemm_tc<<<dim3(V_ / BN, BS_ / BM), 256, gemmSmem>>>(hp, Wout, bout, nullptr,
                                                          (float*)d_out, BS_, V_, D_, 0);
}

// round 4
// speedup vs baseline: 1.7386x; 1.4811x over previous
#include <cuda_runtime.h>
#include <cuda_fp16.h>
#include <math.h>
#include <stdint.h>

// ---------------- constants ----------------
namespace {
constexpr int B_ = 8, S_ = 1024, D_ = 768, H_ = 12, DH_ = 64, L_ = 8, V_ = 1024;
constexpr int COND_ = 256, NACT_ = 4, DPA_ = 64;
constexpr int BS_ = B_ * S_;               // 8192
constexpr int QKV_N = 3 * D_;              // 2304
// mma.sync GEMM tiling
constexpr int BM = 128, BN = 128, BK = 64;
constexpr int STAGE_BYTES = 32768;         // A 16KB + B 16KB per stage
constexpr int GEMM_SMEM = 2 * STAGE_BYTES; // 64KB double buffered
}

// ---------------- scratch (static device globals; no runtime alloc) ----------------
__device__ float  g_x  [BS_ * D_];
__device__ __half g_hh [BS_ * D_];          // LN output (GEMM A operand)
__device__ __half g_qkv[BS_ * QKV_N];       // fused q|k|v, [B*S, 2304]
__device__ __half g_oh [BS_ * D_];          // attention output
__device__ __half g_ffh[BS_ * 4 * D_];      // gelu output
__device__ float  g_a  [B_ * COND_];
__device__ float  g_gv [B_ * D_];
__device__ float  g_bv [B_ * D_];
// fp16 transposed weights, K-major rows [N][K]
__device__ __half g_WqkvT[L_ * QKV_N * D_];
__device__ __half g_WoT  [L_ * D_ * D_];
__device__ __half g_W1T  [L_ * 4 * D_ * D_];
__device__ __half g_W2T  [L_ * D_ * 4 * D_];
__device__ __half g_WoutT[V_ * D_];

// ---------------- small helpers ----------------
__device__ __forceinline__ uint32_t smem_u32(const void* p) {
    uint32_t a;
    asm("{ .reg .u64 t; cvta.to.shared.u64 t, %1; cvt.u32.u64 %0, t; }" : "=r"(a) : "l"(p));
    return a;
}
__device__ __forceinline__ void cp16(uint32_t dst, const void* src) {
    asm volatile("cp.async.cg.shared.global [%0], [%1], 16;" :: "r"(dst), "l"(src) : "memory");
}
__device__ __forceinline__ void cp_commit() {
    asm volatile("cp.async.commit_group;" ::: "memory");
}
template <int N> __device__ __forceinline__ void cp_wait() {
    asm volatile("cp.async.wait_group %0;" :: "n"(N) : "memory");
}
__device__ __forceinline__ void ldm_x4(uint32_t* r, uint32_t addr) {
    asm volatile("ldmatrix.sync.aligned.m8n8.x4.shared.b16 {%0,%1,%2,%3}, [%4];"
                 : "=r"(r[0]), "=r"(r[1]), "=r"(r[2]), "=r"(r[3]) : "r"(addr));
}
__device__ __forceinline__ void mma16816(float* c, const uint32_t* a, const uint32_t* b) {
    asm volatile("mma.sync.aligned.m16n8k16.row.col.f32.f16.f16.f32 "
                 "{%0,%1,%2,%3}, {%4,%5,%6,%7}, {%8,%9}, {%0,%1,%2,%3};"
                 : "+f"(c[0]), "+f"(c[1]), "+f"(c[2]), "+f"(c[3])
                 : "r"(a[0]), "r"(a[1]), "r"(a[2]), "r"(a[3]), "r"(b[0]), "r"(b[1]));
}
__device__ __forceinline__ float gelu_f(float x) {
    float x3 = x * x * x;
    return 0.5f * x * (1.f + tanhf(0.7978845608028654f * (x + 0.044715f * x3)));
}

// ---------------- weight transpose + fp16 convert: W[K,N] -> WT[N,K] ----------------
__global__ __launch_bounds__(256) void k_wt(const float* __restrict__ W,
                                            __half* __restrict__ WT, int K, int N) {
    __shared__ float tl[32][33];
    int nb = blockIdx.x * 32, kb = blockIdx.y * 32;
    int tx = threadIdx.x & 31, ty = threadIdx.x >> 5;   // 32 x 8
    #pragma unroll
    for (int i = 0; i < 32; i += 8)
        tl[ty + i][tx] = W[(size_t)(kb + ty + i) * N + nb + tx];
    __syncthreads();
    #pragma unroll
    for (int i = 0; i < 32; i += 8)
        WT[(size_t)(nb + ty + i) * K + kb + tx] = __float2half_rn(tl[tx][ty + i]);
}

// ---------------- build block-diagonal fused QKV weight, transposed [2304][768] ----------------
__global__ __launch_bounds__(256) void k_wqkv(const float* __restrict__ Wq,
                                              const float* __restrict__ Wk,
                                              const float* __restrict__ Wv,
                                              __half* __restrict__ out) {
    int i = blockIdx.x * 256 + threadIdx.x;         // over QKV_N * D_
    if (i >= QKV_N * D_) return;
    int n = i / D_, k = i % D_;
    int part = n / D_;                              // 0=q,1=k,2=v
    int nn = n % D_;
    int h = nn >> 6, e = nn & 63;
    const float* W = (part == 0) ? Wq : (part == 1) ? Wk : Wv;
    float v = 0.f;
    int d = k - h * DH_;
    if (d >= 0 && d < DH_) v = W[(size_t)(h * DH_ + d) * DH_ + e];
    out[i] = __float2half_rn(v);
}

// ---------------- embedding + sinusoidal PE ----------------
__global__ void k_embed(const int* __restrict__ tokens, const float* __restrict__ emb) {
    int row = blockIdx.x;
    int s = row & (S_ - 1);
    int tok = tokens[row];
    for (int d = threadIdx.x; d < D_; d += blockDim.x) {
        int p2 = d & ~1;
        float freq = expf(-(float)p2 * (9.210340371976184f / (float)D_));
        float ang = (float)s * freq;
        float pe = (d & 1) ? cosf(ang) : sinf(ang);
        g_x[row * D_ + d] = emb[tok * D_ + d] + pe;
    }
}

// ---------------- action embedding gather ----------------
__global__ void k_act(const int* __restrict__ actions, const float* __restrict__ act_emb) {
    int i = blockIdx.x * blockDim.x + threadIdx.x;
    if (i >= B_ * COND_) return;
    int b = i / COND_, c = i % COND_;
    int n = c / DPA_, j = c % DPA_;
    g_a[i] = act_emb[actions[b * NACT_ + n] * DPA_ + j];
}

// ---------------- conditional gain/shift vectors ----------------
__global__ void k_condvec(const float* __restrict__ gw, const float* __restrict__ bw) {
    int i = blockIdx.x * blockDim.x + threadIdx.x;
    if (i >= B_ * D_) return;
    int b = i / D_, d = i % D_;
    const float* ar = g_a + b * COND_;
    float sg = 0.f, sb = 0.f;
    for (int c = 0; c < COND_; c++) {
        float av = ar[c];
        sg += av * gw[c * D_ + d];
        sb += av * bw[c * D_ + d];
    }
    g_gv[i] = sg;
    g_bv[i] = sb;
}

// ---------------- conditional layernorm: g_x -> g_hh (fp16) ----------------
__global__ __launch_bounds__(256) void k_condln() {
    int row = blockIdx.x;
    int b = row >> 10;
    const float* xp = g_x + row * D_;
    int t = threadIdx.x;
    float x0 = xp[t], x1 = xp[t + 256], x2 = xp[t + 512];
    float s1 = x0 + x1 + x2;
    float s2 = x0 * x0 + x1 * x1 + x2 * x2;
    #pragma unroll
    for (int o = 16; o; o >>= 1) {
        s1 += __shfl_xor_sync(0xffffffffu, s1, o);
        s2 += __shfl_xor_sync(0xffffffffu, s2, o);
    }
    __shared__ float rs1[8], rs2[8];
    __shared__ float mu_s, rstd_s;
    int w = t >> 5;
    if ((t & 31) == 0) { rs1[w] = s1; rs2[w] = s2; }
    __syncthreads();
    if (t == 0) {
        float a1 = 0.f, a2 = 0.f;
        #pragma unroll
        for (int i = 0; i < 8; i++) { a1 += rs1[i]; a2 += rs2[i]; }
        float mu = a1 / (float)D_;
        float var = a2 / (float)D_ - mu * mu;
        mu_s = mu;
        rstd_s = rsqrtf(var + 1e-5f);
    }
    __syncthreads();
    float mu = mu_s, rstd = rstd_s;
    const float* gv = g_gv + b * D_;
    const float* bv = g_bv + b * D_;
    __half* hp = g_hh + (size_t)row * D_;
    hp[t]       = __float2half_rn((x0 - mu) * rstd * gv[t]       + bv[t]);
    hp[t + 256] = __float2half_rn((x1 - mu) * rstd * gv[t + 256] + bv[t + 256]);
    hp[t + 512] = __float2half_rn((x2 - mu) * rstd * gv[t + 512] + bv[t + 512]);
}

// ---------------- flash attention (fp16 qkv in, fp16 out) ----------------
__global__ __launch_bounds__(256) void k_flash() {
    extern __shared__ float sm[];
    float* Qs = sm;
    float* Ks = Qs + 64 * 65;
    float* Vs = Ks + 64 * 65;
    float* Ps = Vs + 64 * 65;
    int bh = blockIdx.y;
    int b = bh / H_, hh = bh % H_;
    int qBase = blockIdx.x * 64;
    int t = threadIdx.x;
    int r = t >> 2, g = t & 3;
    const __half* qp = g_qkv + (size_t)(b * S_ + qBase) * QKV_N + hh * DH_;
    #pragma unroll
    for (int u = 0; u < 16; u++) {
        int idx = t + u * 256;
        int i = idx >> 6, d = idx & 63;
        Qs[i * 65 + d] = __half2float(qp[(size_t)i * QKV_N + d]) * 0.125f;
    }
    float m = -1e30f, l = 0.f;
    float acc[16];
    #pragma unroll
    for (int c = 0; c < 16; c++) acc[c] = 0.f;

    for (int kt = 0; kt < S_; kt += 64) {
        const __half* kp = g_qkv + (size_t)(b * S_ + kt) * QKV_N + D_ + hh * DH_;
        const __half* vp = kp + D_;
        __syncthreads();
        #pragma unroll
        for (int u = 0; u < 16; u++) {
            int idx = t + u * 256;
            int i = idx >> 6, d = idx & 63;
            Ks[i * 65 + d] = __half2float(kp[(size_t)i * QKV_N + d]);
            Vs[i * 65 + d] = __half2float(vp[(size_t)i * QKV_N + d]);
        }
        __syncthreads();
        float sv[16];
        #pragma unroll
        for (int jj = 0; jj < 16; jj++) sv[jj] = 0.f;
        for (int d = 0; d < 64; d++) {
            float qd = Qs[r * 65 + d];
            #pragma unroll
            for (int jj = 0; jj < 16; jj++)
                sv[jj] += qd * Ks[(g * 16 + jj) * 65 + d];
        }
        float tmax = sv[0];
        #pragma unroll
        for (int jj = 1; jj < 16; jj++) tmax = fmaxf(tmax, sv[jj]);
        tmax = fmaxf(tmax, __shfl_xor_sync(0xffffffffu, tmax, 1));
        tmax = fmaxf(tmax, __shfl_xor_sync(0xffffffffu, tmax, 2));
        float mnew = fmaxf(m, tmax);
        float corr = expf(m - mnew);
        float psum = 0.f;
        #pragma unroll
        for (int jj = 0; jj < 16; jj++) {
            float p = expf(sv[jj] - mnew);
            psum += p;
            Ps[r * 65 + g * 16 + jj] = p;
        }
        psum += __shfl_xor_sync(0xffffffffu, psum, 1);
        psum += __shfl_xor_sync(0xffffffffu, psum, 2);
        l = l * corr + psum;
        m = mnew;
        #pragma unroll
        for (int c = 0; c < 16; c++) acc[c] *= corr;
        __syncthreads();
        for (int j = 0; j < 64; j++) {
            float pv = Ps[r * 65 + j];
            #pragma unroll
            for (int cc = 0; cc < 16; cc++)
                acc[cc] += pv * Vs[j * 65 + g * 16 + cc];
        }
    }
    float inv = 1.f / l;
    __half* outp = g_oh + (size_t)(b * S_ + qBase + r) * D_ + hh * DH_ + g * 16;
    #pragma unroll
    for (int cc = 0; cc < 16; cc++) outp[cc] = __float2half_rn(acc[cc] * inv);
}

// ---------------- fp16 mma.sync GEMM: C[M,N] = epi(A[M,K] @ Bt[N,K]^T) ----------------
// epi: 0 = +bias -> fp32 Cf;  1 = gelu(+bias) -> fp16 Ch;  2 = +bias+res -> fp32 Cf;
//      3 = plain -> fp16 Ch (no bias)
__global__ __launch_bounds__(256) void k_gemm_mma(const __half* __restrict__ A,
                                                  const __half* __restrict__ Bt,
                                                  const float* __restrict__ bias,
                                                  const float* __restrict__ res,
                                                  float* __restrict__ Cf,
                                                  __half* __restrict__ Ch,
                                                  int M, int N, int K, int epi) {
    extern __shared__ char smem[];
    uint32_t sb = smem_u32(smem);
    int t = threadIdx.x;
    int lane = t & 31, wid = t >> 5;
    int warpM = wid >> 2, warpN = wid & 3;           // 2 x 4 warps
    int rowBase = blockIdx.y * BM, colBase = blockIdx.x * BN;
    const __half* Ag = A + (size_t)rowBase * K;
    const __half* Bg = Bt + (size_t)colBase * K;
    const int nCh = K >> 6;

    float acc[4][4][4];
    #pragma unroll
    for (int i = 0; i < 4; i++)
        #pragma unroll
        for (int j = 0; j < 4; j++)
            #pragma unroll
            for (int c = 0; c < 4; c++) acc[i][j][c] = 0.f;

    // cp.async issue: 4 A chunks + 4 B chunks per thread per stage (16B each)
    auto issue = [&](int ch, int s) {
        uint32_t stage = sb + (uint32_t)s * STAGE_BYTES;
        int kt = ch << 6;
        #pragma unroll
        for (int i = 0; i < 4; i++) {
            int id = t + i * 256;
            int r = id >> 3, c = id & 7;
            uint32_t dst = stage + (uint32_t)(r * 128 + ((c ^ (r & 7)) << 4));
            cp16(dst, Ag + (size_t)r * K + kt + c * 8);
        }
        #pragma unroll
        for (int i = 0; i < 4; i++) {
            int id = t + i * 256;
            int r = id >> 3, c = id & 7;
            uint32_t dst = stage + 16384u + (uint32_t)(r * 128 + ((c ^ (r & 7)) << 4));
            cp16(dst, Bg + (size_t)r * K + kt + c * 8);
        }
        cp_commit();
    };

    issue(0, 0);
    for (int ch = 0; ch < nCh; ch++) {
        int s = ch & 1;
        if (ch + 1 < nCh) { issue(ch + 1, s ^ 1); cp_wait<1>(); }
        else               { cp_wait<0>(); }
        __syncthreads();

        uint32_t aBase = sb + (uint32_t)s * STAGE_BYTES;
        uint32_t bBase = aBase + 16384u;
        int lrA = lane & 15, kbA = lane >> 4;
        int g2 = lane >> 3;
        int rowOffB = ((g2 >> 1) << 3) + (lane & 7);
        int kbB = g2 & 1;
        #pragma unroll
        for (int ks = 0; ks < 4; ks++) {
            uint32_t af[4][4];
            int chunkA = ks * 2 + kbA;
            #pragma unroll
            for (int mi = 0; mi < 4; mi++) {
                int r = warpM * 64 + mi * 16 + lrA;
                ldm_x4(af[mi], aBase + (uint32_t)(r * 128 + ((chunkA ^ (r & 7)) << 4)));
            }
            uint32_t bf[4][2];
            int chunkB = ks * 2 + kbB;
            #pragma unroll
            for (int nh = 0; nh < 2; nh++) {
                int r = warpN * 32 + nh * 16 + rowOffB;
                uint32_t q[4];
                ldm_x4(q, bBase + (uint32_t)(r * 128 + ((chunkB ^ (r & 7)) << 4)));
                bf[nh * 2][0] = q[0];  bf[nh * 2][1] = q[1];
                bf[nh * 2 + 1][0] = q[2]; bf[nh * 2 + 1][1] = q[3];
            }
            #pragma unroll
            for (int mi = 0; mi < 4; mi++)
                #pragma unroll
                for (int ni = 0; ni < 4; ni++)
                    mma16816(acc[mi][ni], af[mi], bf[ni]);
        }
        __syncthreads();
    }

    // epilogue from fragments
    int qr = lane >> 2, qc = lane & 3;
    #pragma unroll
    for (int mi = 0; mi < 4; mi++) {
        #pragma unroll
        for (int ni = 0; ni < 4; ni++) {
            int row0 = rowBase + warpM * 64 + mi * 16 + qr;
            int col  = colBase + warpN * 32 + ni * 8 + qc * 2;
            #pragma unroll
            for (int hrow = 0; hrow < 2; hrow++) {
                int rr = row0 + hrow * 8;
                float v0 = acc[mi][ni][hrow * 2];
                float v1 = acc[mi][ni][hrow * 2 + 1];
                if (epi == 0 || epi == 2) {
                    v0 += bias[col]; v1 += bias[col + 1];
                    if (epi == 2) {
                        const float* rp = res + (size_t)rr * N + col;
                        v0 += rp[0]; v1 += rp[1];
                    }
                    float2 o; o.x = v0; o.y = v1;
                    *(float2*)(Cf + (size_t)rr * N + col) = o;
                } else if (epi == 1) {
                    v0 = gelu_f(v0 + bias[col]);
                    v1 = gelu_f(v1 + bias[col + 1]);
                    *(__half2*)(Ch + (size_t)rr * N + col) = __floats2half2_rn(v0, v1);
                } else {
                    *(__half2*)(Ch + (size_t)rr * N + col) = __floats2half2_rn(v0, v1);
                }
            }
        }
    }
}

// ---------------- launch sequence ----------------
extern "C" void kernel_launch(void* const* d_in, const int* in_sizes, int n_in,
                              void* d_out, int out_size) {
    const int*   tokens  = (const int*)d_in[0];
    const int*   actions = (const int*)d_in[1];
    const float* emb     = (const float*)d_in[2];
    const float* act_emb = (const float*)d_in[3];
    const float* ln1_g   = (const float*)d_in[4];
    const float* ln1_b   = (const float*)d_in[5];
    const float* Wq      = (const float*)d_in[6];
    const float* Wk      = (const float*)d_in[7];
    const float* Wv      = (const float*)d_in[8];
    const float* Wo      = (const float*)d_in[9];
    const float* bo      = (const float*)d_in[10];
    const float* ln2_g   = (const float*)d_in[11];
    const float* ln2_b   = (const float*)d_in[12];
    const float* W1      = (const float*)d_in[13];
    const float* b1      = (const float*)d_in[14];
    const float* W2      = (const float*)d_in[15];
    const float* b2      = (const float*)d_in[16];
    const float* lnf_g   = (const float*)d_in[17];
    const float* lnf_b   = (const float*)d_in[18];
    const float* Wout    = (const float*)d_in[19];
    const float* bout    = (const float*)d_in[20];

    float *xp;
    __half *hhp, *qkvp, *ohp, *ffp, *wqkvT, *woT, *w1T, *w2T, *woutT;
    cudaGetSymbolAddress((void**)&xp,    g_x);
    cudaGetSymbolAddress((void**)&hhp,   g_hh);
    cudaGetSymbolAddress((void**)&qkvp,  g_qkv);
    cudaGetSymbolAddress((void**)&ohp,   g_oh);
    cudaGetSymbolAddress((void**)&ffp,   g_ffh);
    cudaGetSymbolAddress((void**)&wqkvT, g_WqkvT);
    cudaGetSymbolAddress((void**)&woT,   g_WoT);
    cudaGetSymbolAddress((void**)&w1T,   g_W1T);
    cudaGetSymbolAddress((void**)&w2T,   g_W2T);
    cudaGetSymbolAddress((void**)&woutT, g_WoutT);

    const int flashSmem = 4 * 64 * 65 * (int)sizeof(float);   // 66560
    cudaFuncSetAttribute(k_flash, cudaFuncAttributeMaxDynamicSharedMemorySize, flashSmem);
    cudaFuncSetAttribute(k_gemm_mma, cudaFuncAttributeMaxDynamicSharedMemorySize, GEMM_SMEM);

    // weight prep: fp16 transposes + fused block-diag QKV
    for (int l = 0; l < L_; l++) {
        k_wt<<<dim3(D_ / 32, D_ / 32), 256>>>(Wo + (size_t)l * D_ * D_,
                                              woT + (size_t)l * D_ * D_, D_, D_);
        k_wt<<<dim3(4 * D_ / 32, D_ / 32), 256>>>(W1 + (size_t)l * D_ * 4 * D_,
                                                  w1T + (size_t)l * 4 * D_ * D_, D_, 4 * D_);
        k_wt<<<dim3(D_ / 32, 4 * D_ / 32), 256>>>(W2 + (size_t)l * 4 * D_ * D_,
                                                  w2T + (size_t)l * D_ * 4 * D_, 4 * D_, D_);
        k_wqkv<<<(QKV_N * D_ + 255) / 256, 256>>>(Wq + (size_t)l * H_ * DH_ * DH_,
                                                  Wk + (size_t)l * H_ * DH_ * DH_,
                                                  Wv + (size_t)l * H_ * DH_ * DH_,
                                                  wqkvT + (size_t)l * QKV_N * D_);
    }
    k_wt<<<dim3(V_ / 32, D_ / 32), 256>>>(Wout, woutT, D_, V_);

    k_embed<<<BS_, 256>>>(tokens, emb);
    k_act<<<(B_ * COND_ + 255) / 256, 256>>>(actions, act_emb);

    for (int l = 0; l < L_; l++) {
        size_t lnOff = (size_t)l * COND_ * D_;
        k_condvec<<<(B_ * D_ + 255) / 256, 256>>>(ln1_g + lnOff, ln1_b + lnOff);
        k_condln<<<BS_, 256>>>();
        // fused qkv = h @ WqkvT^T  (block-diagonal per-head projections)
        k_gemm_mma<<<dim3(QKV_N / BN, BS_ / BM), 256, GEMM_SMEM>>>(
            hhp, wqkvT + (size_t)l * QKV_N * D_, nullptr, nullptr, nullptr, qkvp,
            BS_, QKV_N, D_, 3);
        k_flash<<<dim3(S_ / 64, B_ * H_), 256, flashSmem>>>();
        // x = x + o @ Wo + bo
        k_gemm_mma<<<dim3(D_ / BN, BS_ / BM), 256, GEMM_SMEM>>>(
            ohp, woT + (size_t)l * D_ * D_, bo + l * D_, xp, xp, nullptr,
            BS_, D_, D_, 2);
        k_condvec<<<(B_ * D_ + 255) / 256, 256>>>(ln2_g + lnOff, ln2_b + lnOff);
        k_condln<<<BS_, 256>>>();
        // ff = gelu(h @ W1 + b1)  (fp16 out)
        k_gemm_mma<<<dim3(4 * D_ / BN, BS_ / BM), 256, GEMM_SMEM>>>(
            hhp, w1T + (size_t)l * 4 * D_ * D_, b1 + l * 4 * D_, nullptr, nullptr, ffp,
            BS_, 4 * D_, D_, 1);
        // x = x + ff @ W2 + b2
        k_gemm_mma<<<dim3(D_ / BN, BS_ / BM), 256, GEMM_SMEM>>>(
            ffp, w2T + (size_t)l * D_ * 4 * D_, b2 + l * D_, xp, xp, nullptr,
            BS_, D_, 4 * D_, 2);
    }
    k_condvec<<<(B_ * D_ + 255) / 256, 256>>>(lnf_g, lnf_b);
    k_condln<<<BS_, 256>>>();
    // out = h @ Wout + bout
    k_gemm_mma<<<dim3(V_ / BN, BS_ / BM), 256, GEMM_SMEM>>>(
        hhp, woutT, bout, nullptr, (float*)d_out, nullptr,
        BS_, V_, D_, 0);
}

// round 5
// speedup vs baseline: 10.4918x; 6.0346x over previous
#include <cuda_runtime.h>
#include <cuda_fp16.h>
#include <math.h>
#include <stdint.h>

// ---------------- constants ----------------
namespace {
constexpr int B_ = 8, S_ = 1024, D_ = 768, H_ = 12, DH_ = 64, L_ = 8, V_ = 1024;
constexpr int COND_ = 256, NACT_ = 4, DPA_ = 64;
constexpr int BS_ = B_ * S_;               // 8192
constexpr int QKV_N = 3 * D_;              // 2304
// mma.sync GEMM tiling
constexpr int BM = 128, BN = 128;
constexpr int STAGE_BYTES = 32768;         // A 16KB + B 16KB per stage
constexpr int GEMM_SMEM = 2 * STAGE_BYTES; // 64KB double buffered
// flash tiling
constexpr int FL_SMEM = 16384 + 2 * 16384; // Q 16KB + 2 stages of (K 8KB + V 8KB)
}

// ---------------- scratch (static device globals; no runtime alloc) ----------------
__device__ float  g_x  [BS_ * D_];
__device__ __half g_hh [BS_ * D_];
__device__ __half g_qkv[BS_ * QKV_N];
__device__ __half g_oh [BS_ * D_];
__device__ __half g_ffh[BS_ * 4 * D_];
__device__ float  g_a  [B_ * COND_];
__device__ float  g_gv [B_ * D_];
__device__ float  g_bv [B_ * D_];
__device__ __half g_WqkvT[L_ * QKV_N * D_];
__device__ __half g_WoT  [L_ * D_ * D_];
__device__ __half g_W1T  [L_ * 4 * D_ * D_];
__device__ __half g_W2T  [L_ * D_ * 4 * D_];
__device__ __half g_WoutT[V_ * D_];

// ---------------- small helpers ----------------
__device__ __forceinline__ uint32_t smem_u32(const void* p) {
    uint32_t a;
    asm("{ .reg .u64 t; cvta.to.shared.u64 t, %1; cvt.u32.u64 %0, t; }" : "=r"(a) : "l"(p));
    return a;
}
__device__ __forceinline__ void cp16(uint32_t dst, const void* src) {
    asm volatile("cp.async.cg.shared.global [%0], [%1], 16;" :: "r"(dst), "l"(src) : "memory");
}
__device__ __forceinline__ void cp_commit() {
    asm volatile("cp.async.commit_group;" ::: "memory");
}
template <int N> __device__ __forceinline__ void cp_wait() {
    asm volatile("cp.async.wait_group %0;" :: "n"(N) : "memory");
}
__device__ __forceinline__ void ldm_x4(uint32_t* r, uint32_t addr) {
    asm volatile("ldmatrix.sync.aligned.m8n8.x4.shared.b16 {%0,%1,%2,%3}, [%4];"
                 : "=r"(r[0]), "=r"(r[1]), "=r"(r[2]), "=r"(r[3]) : "r"(addr));
}
__device__ __forceinline__ void ldm_x4_t(uint32_t* r, uint32_t addr) {
    asm volatile("ldmatrix.sync.aligned.m8n8.x4.trans.shared.b16 {%0,%1,%2,%3}, [%4];"
                 : "=r"(r[0]), "=r"(r[1]), "=r"(r[2]), "=r"(r[3]) : "r"(addr));
}
__device__ __forceinline__ void mma16816(float* c, const uint32_t* a, const uint32_t* b) {
    asm volatile("mma.sync.aligned.m16n8k16.row.col.f32.f16.f16.f32 "
                 "{%0,%1,%2,%3}, {%4,%5,%6,%7}, {%8,%9}, {%0,%1,%2,%3};"
                 : "+f"(c[0]), "+f"(c[1]), "+f"(c[2]), "+f"(c[3])
                 : "r"(a[0]), "r"(a[1]), "r"(a[2]), "r"(a[3]), "r"(b[0]), "r"(b[1]));
}
__device__ __forceinline__ uint32_t h2exp2_bits(__half2 x) {
    uint32_t y;
    asm("ex2.approx.f16x2 %0, %1;" : "=r"(y) : "r"(*(uint32_t*)&x));
    return y;
}
__device__ __forceinline__ float gelu_f(float x) {
    float x3 = x * x * x;
    return 0.5f * x * (1.f + tanhf(0.7978845608028654f * (x + 0.044715f * x3)));
}

// ---------------- weight transpose + fp16 convert: W[K,N] -> WT[N,K] ----------------
__global__ __launch_bounds__(256) void k_wt(const float* __restrict__ W,
                                            __half* __restrict__ WT, int K, int N) {
    __shared__ float tl[32][33];
    int nb = blockIdx.x * 32, kb = blockIdx.y * 32;
    int tx = threadIdx.x & 31, ty = threadIdx.x >> 5;
    #pragma unroll
    for (int i = 0; i < 32; i += 8)
        tl[ty + i][tx] = W[(size_t)(kb + ty + i) * N + nb + tx];
    __syncthreads();
    #pragma unroll
    for (int i = 0; i < 32; i += 8)
        WT[(size_t)(nb + ty + i) * K + kb + tx] = __float2half_rn(tl[tx][ty + i]);
}

// ---------------- block-diagonal fused QKV weight, transposed [2304][768] ----------------
__global__ __launch_bounds__(256) void k_wqkv(const float* __restrict__ Wq,
                                              const float* __restrict__ Wk,
                                              const float* __restrict__ Wv,
                                              __half* __restrict__ out) {
    int i = blockIdx.x * 256 + threadIdx.x;
    if (i >= QKV_N * D_) return;
    int n = i / D_, k = i % D_;
    int part = n / D_;
    int nn = n % D_;
    int h = nn >> 6, e = nn & 63;
    const float* W = (part == 0) ? Wq : (part == 1) ? Wk : Wv;
    float v = 0.f;
    int d = k - h * DH_;
    if (d >= 0 && d < DH_) v = W[(size_t)(h * DH_ + d) * DH_ + e];
    out[i] = __float2half_rn(v);
}

// ---------------- embedding + sinusoidal PE ----------------
__global__ void k_embed(const int* __restrict__ tokens, const float* __restrict__ emb) {
    int row = blockIdx.x;
    int s = row & (S_ - 1);
    int tok = tokens[row];
    for (int d = threadIdx.x; d < D_; d += blockDim.x) {
        int p2 = d & ~1;
        float freq = expf(-(float)p2 * (9.210340371976184f / (float)D_));
        float ang = (float)s * freq;
        float pe = (d & 1) ? cosf(ang) : sinf(ang);
        g_x[row * D_ + d] = emb[tok * D_ + d] + pe;
    }
}

// ---------------- action embedding gather ----------------
__global__ void k_act(const int* __restrict__ actions, const float* __restrict__ act_emb) {
    int i = blockIdx.x * blockDim.x + threadIdx.x;
    if (i >= B_ * COND_) return;
    int b = i / COND_, c = i % COND_;
    int n = c / DPA_, j = c % DPA_;
    g_a[i] = act_emb[actions[b * NACT_ + n] * DPA_ + j];
}

// ---------------- conditional gain/shift vectors ----------------
__global__ void k_condvec(const float* __restrict__ gw, const float* __restrict__ bw) {
    int i = blockIdx.x * blockDim.x + threadIdx.x;
    if (i >= B_ * D_) return;
    int b = i / D_, d = i % D_;
    const float* ar = g_a + b * COND_;
    float sg = 0.f, sb = 0.f;
    for (int c = 0; c < COND_; c++) {
        float av = ar[c];
        sg += av * gw[c * D_ + d];
        sb += av * bw[c * D_ + d];
    }
    g_gv[i] = sg;
    g_bv[i] = sb;
}

// ---------------- conditional layernorm: g_x -> g_hh (fp16) ----------------
__global__ __launch_bounds__(256) void k_condln() {
    int row = blockIdx.x;
    int b = row >> 10;
    const float* xp = g_x + row * D_;
    int t = threadIdx.x;
    float x0 = xp[t], x1 = xp[t + 256], x2 = xp[t + 512];
    float s1 = x0 + x1 + x2;
    float s2 = x0 * x0 + x1 * x1 + x2 * x2;
    #pragma unroll
    for (int o = 16; o; o >>= 1) {
        s1 += __shfl_xor_sync(0xffffffffu, s1, o);
        s2 += __shfl_xor_sync(0xffffffffu, s2, o);
    }
    __shared__ float rs1[8], rs2[8];
    __shared__ float mu_s, rstd_s;
    int w = t >> 5;
    if ((t & 31) == 0) { rs1[w] = s1; rs2[w] = s2; }
    __syncthreads();
    if (t == 0) {
        float a1 = 0.f, a2 = 0.f;
        #pragma unroll
        for (int i = 0; i < 8; i++) { a1 += rs1[i]; a2 += rs2[i]; }
        float mu = a1 / (float)D_;
        float var = a2 / (float)D_ - mu * mu;
        mu_s = mu;
        rstd_s = rsqrtf(var + 1e-5f);
    }
    __syncthreads();
    float mu = mu_s, rstd = rstd_s;
    const float* gv = g_gv + b * D_;
    const float* bv = g_bv + b * D_;
    __half* hp = g_hh + (size_t)row * D_;
    hp[t]       = __float2half_rn((x0 - mu) * rstd * gv[t]       + bv[t]);
    hp[t + 256] = __float2half_rn((x1 - mu) * rstd * gv[t + 256] + bv[t + 256]);
    hp[t + 512] = __float2half_rn((x2 - mu) * rstd * gv[t + 512] + bv[t + 512]);
}

// ---------------- tensor-core flash attention ----------------
// grid (S/128, B*H); 8 warps x 16 Q rows; K/V tiles 64 x 64, cp.async double buffer.
__global__ __launch_bounds__(256) void k_flash_tc() {
    extern __shared__ char fsm[];
    uint32_t sb = smem_u32(fsm);
    int t = threadIdx.x, lane = t & 31, wid = t >> 5;
    int bh = blockIdx.y;
    int b = bh / H_, h = bh % H_;
    int qBase = blockIdx.x * 128;
    int qr = lane >> 2, qc = lane & 3;

    // Q tile: 128 x 64 fp16, swizzled rows of 128B
    const __half* qg = g_qkv + (size_t)(b * S_ + qBase) * QKV_N + h * DH_;
    #pragma unroll
    for (int i = 0; i < 4; i++) {
        int id = t + i * 256;
        int r = id >> 3, c8 = id & 7;
        cp16(sb + (uint32_t)(r * 128 + ((c8 ^ (r & 7)) << 4)), qg + (size_t)r * QKV_N + c8 * 8);
    }
    auto issueKV = [&](int kt, int s) {
        uint32_t st = sb + 16384u + (uint32_t)s * 16384u;
        const __half* kg = g_qkv + (size_t)(b * S_ + kt) * QKV_N + D_ + h * DH_;
        const __half* vg = kg + D_;
        #pragma unroll
        for (int i = 0; i < 2; i++) {
            int id = t + i * 256;
            int r = id >> 3, c8 = id & 7;
            cp16(st + (uint32_t)(r * 128 + ((c8 ^ (r & 7)) << 4)), kg + (size_t)r * QKV_N + c8 * 8);
        }
        #pragma unroll
        for (int i = 0; i < 2; i++) {
            int id = t + i * 256;
            int r = id >> 3, c8 = id & 7;
            cp16(st + 8192u + (uint32_t)(r * 128 + ((c8 ^ (r & 7)) << 4)), vg + (size_t)r * QKV_N + c8 * 8);
        }
        cp_commit();   // group includes any prior uncommitted cps (Q on first call)
    };
    issueKV(0, 0);

    uint32_t qa[4][4];
    float sfr[8][4];
    float o[8][4];
    #pragma unroll
    for (int j = 0; j < 8; j++)
        #pragma unroll
        for (int c = 0; c < 4; c++) o[j][c] = 0.f;
    float m_lo = -1e30f, m_hi = -1e30f, l_lo = 0.f, l_hi = 0.f;

    const int nT = S_ / 64;
    for (int tt = 0; tt < nT; tt++) {
        int st = tt & 1;
        if (tt + 1 < nT) { issueKV((tt + 1) * 64, st ^ 1); cp_wait<1>(); }
        else             { cp_wait<0>(); }
        __syncthreads();
        if (tt == 0) {
            // load Q a-frags once (rows wid*16..+15), scale by 0.125*log2(e)
            const __half2 sc2 = __float2half2_rn(0.1803368801f);
            #pragma unroll
            for (int ks = 0; ks < 4; ks++) {
                int r = wid * 16 + (lane & 15);
                int chunk = ks * 2 + (lane >> 4);
                ldm_x4(qa[ks], sb + (uint32_t)(r * 128 + ((chunk ^ (r & 7)) << 4)));
                #pragma unroll
                for (int j = 0; j < 4; j++) {
                    __half2 hv = *(__half2*)&qa[ks][j];
                    hv = __hmul2(hv, sc2);
                    qa[ks][j] = *(uint32_t*)&hv;
                }
            }
        }
        uint32_t kBase = sb + 16384u + (uint32_t)st * 16384u;
        uint32_t vBase = kBase + 8192u;

        // S = Qs @ K^T  (scaled domain)
        #pragma unroll
        for (int j = 0; j < 8; j++)
            #pragma unroll
            for (int c = 0; c < 4; c++) sfr[j][c] = 0.f;
        {
            int g2 = lane >> 3;
            int rowB = ((g2 >> 1) << 3) + (lane & 7);
            int kb = g2 & 1;
            #pragma unroll
            for (int ks = 0; ks < 4; ks++) {
                #pragma unroll
                for (int nh = 0; nh < 4; nh++) {
                    int r = nh * 16 + rowB;
                    int chunk = ks * 2 + kb;
                    uint32_t q4[4];
                    ldm_x4(q4, kBase + (uint32_t)(r * 128 + ((chunk ^ (r & 7)) << 4)));
                    uint32_t b0[2] = { q4[0], q4[1] };
                    uint32_t b1[2] = { q4[2], q4[3] };
                    mma16816(sfr[nh * 2],     qa[ks], b0);
                    mma16816(sfr[nh * 2 + 1], qa[ks], b1);
                }
            }
        }
        // online softmax (exp2 domain), fp16 P
        float tl = sfr[0][0], th = sfr[0][2];
        #pragma unroll
        for (int j = 0; j < 8; j++) {
            tl = fmaxf(tl, fmaxf(sfr[j][0], sfr[j][1]));
            th = fmaxf(th, fmaxf(sfr[j][2], sfr[j][3]));
        }
        tl = fmaxf(tl, __shfl_xor_sync(0xffffffffu, tl, 1));
        tl = fmaxf(tl, __shfl_xor_sync(0xffffffffu, tl, 2));
        th = fmaxf(th, __shfl_xor_sync(0xffffffffu, th, 1));
        th = fmaxf(th, __shfl_xor_sync(0xffffffffu, th, 2));
        float mn_lo = fmaxf(m_lo, tl), mn_hi = fmaxf(m_hi, th);
        float corr_lo = exp2f(m_lo - mn_lo), corr_hi = exp2f(m_hi - mn_hi);
        uint32_t ph[8][2];
        float ps_lo = 0.f, ps_hi = 0.f;
        #pragma unroll
        for (int j = 0; j < 8; j++) {
            __half2 e0h = __floats2half2_rn(sfr[j][0] - mn_lo, sfr[j][1] - mn_lo);
            __half2 e1h = __floats2half2_rn(sfr[j][2] - mn_hi, sfr[j][3] - mn_hi);
            ph[j][0] = h2exp2_bits(e0h);
            ph[j][1] = h2exp2_bits(e1h);
            float2 f0 = __half22float2(*(__half2*)&ph[j][0]);
            float2 f1 = __half22float2(*(__half2*)&ph[j][1]);
            ps_lo += f0.x + f0.y;
            ps_hi += f1.x + f1.y;
        }
        l_lo = l_lo * corr_lo + ps_lo;
        l_hi = l_hi * corr_hi + ps_hi;
        m_lo = mn_lo; m_hi = mn_hi;
        #pragma unroll
        for (int j = 0; j < 8; j++) {
            o[j][0] *= corr_lo; o[j][1] *= corr_lo;
            o[j][2] *= corr_hi; o[j][3] *= corr_hi;
        }
        // O += P @ V  (V via trans ldmatrix from row-major [k][dh])
        #pragma unroll
        for (int ks = 0; ks < 4; ks++) {
            uint32_t pa[4] = { ph[2 * ks][0], ph[2 * ks][1], ph[2 * ks + 1][0], ph[2 * ks + 1][1] };
            #pragma unroll
            for (int jp = 0; jp < 4; jp++) {
                int r = ks * 16 + (lane & 15);
                int chunk = jp * 2 + (lane >> 4);
                uint32_t q4[4];
                ldm_x4_t(q4, vBase + (uint32_t)(r * 128 + ((chunk ^ (r & 7)) << 4)));
                uint32_t b0[2] = { q4[0], q4[1] };
                uint32_t b1[2] = { q4[2], q4[3] };
                mma16816(o[2 * jp],     pa, b0);
                mma16816(o[2 * jp + 1], pa, b1);
            }
        }
        __syncthreads();
    }
    // finalize
    l_lo += __shfl_xor_sync(0xffffffffu, l_lo, 1);
    l_lo += __shfl_xor_sync(0xffffffffu, l_lo, 2);
    l_hi += __shfl_xor_sync(0xffffffffu, l_hi, 1);
    l_hi += __shfl_xor_sync(0xffffffffu, l_hi, 2);
    float inv_lo = 1.f / l_lo, inv_hi = 1.f / l_hi;
    int rlo = b * S_ + qBase + wid * 16 + qr;
    #pragma unroll
    for (int j = 0; j < 8; j++) {
        int col = h * DH_ + j * 8 + qc * 2;
        *(__half2*)(g_oh + (size_t)rlo * D_ + col) =
            __floats2half2_rn(o[j][0] * inv_lo, o[j][1] * inv_lo);
        *(__half2*)(g_oh + (size_t)(rlo + 8) * D_ + col) =
            __floats2half2_rn(o[j][2] * inv_hi, o[j][3] * inv_hi);
    }
}

// ---------------- fp16 mma.sync GEMM: C[M,N] = epi(A[M,K] @ Bt[N,K]^T) ----------------
// epi: 0 = +bias -> fp32 Cf;  1 = gelu(+bias) -> fp16 Ch;  2 = +bias+res -> fp32 Cf;
//      3 = plain -> fp16 Ch
__global__ __launch_bounds__(256) void k_gemm_mma(const __half* __restrict__ A,
                                                  const __half* __restrict__ Bt,
                                                  const float* __restrict__ bias,
                                                  const float* __restrict__ res,
                                                  float* __restrict__ Cf,
                                                  __half* __restrict__ Ch,
                                                  int M, int N, int K, int epi) {
    extern __shared__ char smem[];
    uint32_t sb = smem_u32(smem);
    int t = threadIdx.x;
    int lane = t & 31, wid = t >> 5;
    int warpM = wid >> 2, warpN = wid & 3;
    int rowBase = blockIdx.y * BM, colBase = blockIdx.x * BN;
    const __half* Ag = A + (size_t)rowBase * K;
    const __half* Bg = Bt + (size_t)colBase * K;
    const int nCh = K >> 6;

    float acc[4][4][4];
    #pragma unroll
    for (int i = 0; i < 4; i++)
        #pragma unroll
        for (int j = 0; j < 4; j++)
            #pragma unroll
            for (int c = 0; c < 4; c++) acc[i][j][c] = 0.f;

    auto issue = [&](int ch, int s) {
        uint32_t stage = sb + (uint32_t)s * STAGE_BYTES;
        int kt = ch << 6;
        #pragma unroll
        for (int i = 0; i < 4; i++) {
            int id = t + i * 256;
            int r = id >> 3, c = id & 7;
            cp16(stage + (uint32_t)(r * 128 + ((c ^ (r & 7)) << 4)), Ag + (size_t)r * K + kt + c * 8);
        }
        #pragma unroll
        for (int i = 0; i < 4; i++) {
            int id = t + i * 256;
            int r = id >> 3, c = id & 7;
            cp16(stage + 16384u + (uint32_t)(r * 128 + ((c ^ (r & 7)) << 4)), Bg + (size_t)r * K + kt + c * 8);
        }
        cp_commit();
    };

    issue(0, 0);
    for (int ch = 0; ch < nCh; ch++) {
        int s = ch & 1;
        if (ch + 1 < nCh) { issue(ch + 1, s ^ 1); cp_wait<1>(); }
        else               { cp_wait<0>(); }
        __syncthreads();

        uint32_t aBase = sb + (uint32_t)s * STAGE_BYTES;
        uint32_t bBase = aBase + 16384u;
        int lrA = lane & 15, kbA = lane >> 4;
        int g2 = lane >> 3;
        int rowOffB = ((g2 >> 1) << 3) + (lane & 7);
        int kbB = g2 & 1;
        #pragma unroll
        for (int ks = 0; ks < 4; ks++) {
            uint32_t af[4][4];
            int chunkA = ks * 2 + kbA;
            #pragma unroll
            for (int mi = 0; mi < 4; mi++) {
                int r = warpM * 64 + mi * 16 + lrA;
                ldm_x4(af[mi], aBase + (uint32_t)(r * 128 + ((chunkA ^ (r & 7)) << 4)));
            }
            uint32_t bf[4][2];
            int chunkB = ks * 2 + kbB;
            #pragma unroll
            for (int nh = 0; nh < 2; nh++) {
                int r = warpN * 32 + nh * 16 + rowOffB;
                uint32_t q[4];
                ldm_x4(q, bBase + (uint32_t)(r * 128 + ((chunkB ^ (r & 7)) << 4)));
                bf[nh * 2][0] = q[0];     bf[nh * 2][1] = q[1];
                bf[nh * 2 + 1][0] = q[2]; bf[nh * 2 + 1][1] = q[3];
            }
            #pragma unroll
            for (int mi = 0; mi < 4; mi++)
                #pragma unroll
                for (int ni = 0; ni < 4; ni++)
                    mma16816(acc[mi][ni], af[mi], bf[ni]);
        }
        __syncthreads();
    }

    int qr = lane >> 2, qc = lane & 3;
    #pragma unroll
    for (int mi = 0; mi < 4; mi++) {
        #pragma unroll
        for (int ni = 0; ni < 4; ni++) {
            int row0 = rowBase + warpM * 64 + mi * 16 + qr;
            int col  = colBase + warpN * 32 + ni * 8 + qc * 2;
            #pragma unroll
            for (int hrow = 0; hrow < 2; hrow++) {
                int rr = row0 + hrow * 8;
                float v0 = acc[mi][ni][hrow * 2];
                float v1 = acc[mi][ni][hrow * 2 + 1];
                if (epi == 0 || epi == 2) {
                    v0 += bias[col]; v1 += bias[col + 1];
                    if (epi == 2) {
                        const float* rp = res + (size_t)rr * N + col;
                        v0 += rp[0]; v1 += rp[1];
                    }
                    float2 ov; ov.x = v0; ov.y = v1;
                    *(float2*)(Cf + (size_t)rr * N + col) = ov;
                } else if (epi == 1) {
                    v0 = gelu_f(v0 + bias[col]);
                    v1 = gelu_f(v1 + bias[col + 1]);
                    *(__half2*)(Ch + (size_t)rr * N + col) = __floats2half2_rn(v0, v1);
                } else {
                    *(__half2*)(Ch + (size_t)rr * N + col) = __floats2half2_rn(v0, v1);
                }
            }
        }
    }
}

// ---------------- launch sequence ----------------
extern "C" void kernel_launch(void* const* d_in, const int* in_sizes, int n_in,
                              void* d_out, int out_size) {
    const int*   tokens  = (const int*)d_in[0];
    const int*   actions = (const int*)d_in[1];
    const float* emb     = (const float*)d_in[2];
    const float* act_emb = (const float*)d_in[3];
    const float* ln1_g   = (const float*)d_in[4];
    const float* ln1_b   = (const float*)d_in[5];
    const float* Wq      = (const float*)d_in[6];
    const float* Wk      = (const float*)d_in[7];
    const float* Wv      = (const float*)d_in[8];
    const float* Wo      = (const float*)d_in[9];
    const float* bo      = (const float*)d_in[10];
    const float* ln2_g   = (const float*)d_in[11];
    const float* ln2_b   = (const float*)d_in[12];
    const float* W1      = (const float*)d_in[13];
    const float* b1      = (const float*)d_in[14];
    const float* W2      = (const float*)d_in[15];
    const float* b2      = (const float*)d_in[16];
    const float* lnf_g   = (const float*)d_in[17];
    const float* lnf_b   = (const float*)d_in[18];
    const float* Wout    = (const float*)d_in[19];
    const float* bout    = (const float*)d_in[20];

    float *xp;
    __half *hhp, *qkvp, *ohp, *ffp, *wqkvT, *woT, *w1T, *w2T, *woutT;
    cudaGetSymbolAddress((void**)&xp,    g_x);
    cudaGetSymbolAddress((void**)&hhp,   g_hh);
    cudaGetSymbolAddress((void**)&qkvp,  g_qkv);
    cudaGetSymbolAddress((void**)&ohp,   g_oh);
    cudaGetSymbolAddress((void**)&ffp,   g_ffh);
    cudaGetSymbolAddress((void**)&wqkvT, g_WqkvT);
    cudaGetSymbolAddress((void**)&woT,   g_WoT);
    cudaGetSymbolAddress((void**)&w1T,   g_W1T);
    cudaGetSymbolAddress((void**)&w2T,   g_W2T);
    cudaGetSymbolAddress((void**)&woutT, g_WoutT);

    cudaFuncSetAttribute(k_flash_tc, cudaFuncAttributeMaxDynamicSharedMemorySize, FL_SMEM);
    cudaFuncSetAttribute(k_gemm_mma, cudaFuncAttributeMaxDynamicSharedMemorySize, GEMM_SMEM);

    for (int l = 0; l < L_; l++) {
        k_wt<<<dim3(D_ / 32, D_ / 32), 256>>>(Wo + (size_t)l * D_ * D_,
                                              woT + (size_t)l * D_ * D_, D_, D_);
        k_wt<<<dim3(4 * D_ / 32, D_ / 32), 256>>>(W1 + (size_t)l * D_ * 4 * D_,
                                                  w1T + (size_t)l * 4 * D_ * D_, D_, 4 * D_);
        k_wt<<<dim3(D_ / 32, 4 * D_ / 32), 256>>>(W2 + (size_t)l * 4 * D_ * D_,
                                                  w2T + (size_t)l * D_ * 4 * D_, 4 * D_, D_);
        k_wqkv<<<(QKV_N * D_ + 255) / 256, 256>>>(Wq + (size_t)l * H_ * DH_ * DH_,
                                                  Wk + (size_t)l * H_ * DH_ * DH_,
                                                  Wv + (size_t)l * H_ * DH_ * DH_,
                                                  wqkvT + (size_t)l * QKV_N * D_);
    }
    k_wt<<<dim3(V_ / 32, D_ / 32), 256>>>(Wout, woutT, D_, V_);

    k_embed<<<BS_, 256>>>(tokens, emb);
    k_act<<<(B_ * COND_ + 255) / 256, 256>>>(actions, act_emb);

    for (int l = 0; l < L_; l++) {
        size_t lnOff = (size_t)l * COND_ * D_;
        k_condvec<<<(B_ * D_ + 255) / 256, 256>>>(ln1_g + lnOff, ln1_b + lnOff);
        k_condln<<<BS_, 256>>>();
        k_gemm_mma<<<dim3(QKV_N / BN, BS_ / BM), 256, GEMM_SMEM>>>(
            hhp, wqkvT + (size_t)l * QKV_N * D_, nullptr, nullptr, nullptr, qkvp,
            BS_, QKV_N, D_, 3);
        k_flash_tc<<<dim3(S_ / 128, B_ * H_), 256, FL_SMEM>>>();
        k_gemm_mma<<<dim3(D_ / BN, BS_ / BM), 256, GEMM_SMEM>>>(
            ohp, woT + (size_t)l * D_ * D_, bo + l * D_, xp, xp, nullptr,
            BS_, D_, D_, 2);
        k_condvec<<<(B_ * D_ + 255) / 256, 256>>>(ln2_g + lnOff, ln2_b + lnOff);
        k_condln<<<BS_, 256>>>();
        k_gemm_mma<<<dim3(4 * D_ / BN, BS_ / BM), 256, GEMM_SMEM>>>(
            hhp, w1T + (size_t)l * 4 * D_ * D_, b1 + l * 4 * D_, nullptr, nullptr, ffp,
            BS_, 4 * D_, D_, 1);
        k_gemm_mma<<<dim3(D_ / BN, BS_ / BM), 256, GEMM_SMEM>>>(
            ffp, w2T + (size_t)l * D_ * 4 * D_, b2 + l * D_, xp, xp, nullptr,
            BS_, D_, 4 * D_, 2);
    }
    k_condvec<<<(B_ * D_ + 255) / 256, 256>>>(lnf_g, lnf_b);
    k_condln<<<BS_, 256>>>();
    k_gemm_mma<<<dim3(V_ / BN, BS_ / BM), 256, GEMM_SMEM>>>(
        hhp, woutT, bout, nullptr, (float*)d_out, nullptr,
        BS_, V_, D_, 0);
}

// round 6
// speedup vs baseline: 13.9101x; 1.3258x over previous
#include <cuda_runtime.h>
#include <cuda_fp16.h>
#include <math.h>
#include <stdint.h>

// ---------------- constants ----------------
namespace {
constexpr int B_ = 8, S_ = 1024, D_ = 768, H_ = 12, DH_ = 64, L_ = 8, V_ = 1024;
constexpr int COND_ = 256, NACT_ = 4, DPA_ = 64;
constexpr int BS_ = B_ * S_;               // 8192
constexpr int QKV_N = 3 * D_;              // 2304
constexpr int NSLOT = 2 * L_ + 1;          // 17 cond-LN slots
// mma.sync GEMM tiling
constexpr int BM = 128, BN = 128;
constexpr int STAGE_BYTES = 32768;         // A 16KB + B 16KB per stage
constexpr int NST = 3;
constexpr int GEMM_SMEM = NST * STAGE_BYTES; // 96KB, 3-stage
// flash tiling
constexpr int FL_SMEM = 16384 + 2 * 16384; // Q 16KB + 2 stages of (K 8KB + V 8KB)
}

// ---------------- scratch (static device globals; no runtime alloc) ----------------
__device__ float  g_x  [BS_ * D_];
__device__ float  g_pe [S_ * D_];
__device__ __half g_hh [BS_ * D_];
__device__ __half g_qkv[BS_ * QKV_N];
__device__ __half g_oh [BS_ * D_];
__device__ __half g_ffh[BS_ * 4 * D_];
__device__ float  g_a  [B_ * COND_];
__device__ float  g_gvA[NSLOT * B_ * D_];
__device__ float  g_bvA[NSLOT * B_ * D_];
__device__ __half g_WqkvC[L_ * QKV_N * 128];   // compact block-diag, [N][128]
__device__ __half g_WoT  [L_ * D_ * D_];
__device__ __half g_W1T  [L_ * 4 * D_ * D_];
__device__ __half g_W2T  [L_ * D_ * 4 * D_];
__device__ __half g_WoutT[V_ * D_];

// ---------------- small helpers ----------------
__device__ __forceinline__ uint32_t smem_u32(const void* p) {
    uint32_t a;
    asm("{ .reg .u64 t; cvta.to.shared.u64 t, %1; cvt.u32.u64 %0, t; }" : "=r"(a) : "l"(p));
    return a;
}
__device__ __forceinline__ void cp16(uint32_t dst, const void* src) {
    asm volatile("cp.async.cg.shared.global [%0], [%1], 16;" :: "r"(dst), "l"(src) : "memory");
}
__device__ __forceinline__ void cp_commit() {
    asm volatile("cp.async.commit_group;" ::: "memory");
}
template <int N> __device__ __forceinline__ void cp_wait() {
    asm volatile("cp.async.wait_group %0;" :: "n"(N) : "memory");
}
__device__ __forceinline__ void ldm_x4(uint32_t* r, uint32_t addr) {
    asm volatile("ldmatrix.sync.aligned.m8n8.x4.shared.b16 {%0,%1,%2,%3}, [%4];"
                 : "=r"(r[0]), "=r"(r[1]), "=r"(r[2]), "=r"(r[3]) : "r"(addr));
}
__device__ __forceinline__ void ldm_x4_t(uint32_t* r, uint32_t addr) {
    asm volatile("ldmatrix.sync.aligned.m8n8.x4.trans.shared.b16 {%0,%1,%2,%3}, [%4];"
                 : "=r"(r[0]), "=r"(r[1]), "=r"(r[2]), "=r"(r[3]) : "r"(addr));
}
__device__ __forceinline__ void mma16816(float* c, const uint32_t* a, const uint32_t* b) {
    asm volatile("mma.sync.aligned.m16n8k16.row.col.f32.f16.f16.f32 "
                 "{%0,%1,%2,%3}, {%4,%5,%6,%7}, {%8,%9}, {%0,%1,%2,%3};"
                 : "+f"(c[0]), "+f"(c[1]), "+f"(c[2]), "+f"(c[3])
                 : "r"(a[0]), "r"(a[1]), "r"(a[2]), "r"(a[3]), "r"(b[0]), "r"(b[1]));
}
__device__ __forceinline__ uint32_t h2exp2_bits(__half2 x) {
    uint32_t y;
    asm("ex2.approx.f16x2 %0, %1;" : "=r"(y) : "r"(*(uint32_t*)&x));
    return y;
}
__device__ __forceinline__ float gelu_f(float x) {
    float x3 = x * x * x;
    return 0.5f * x * (1.f + tanhf(0.7978845608028654f * (x + 0.044715f * x3)));
}

// ---------------- batched weight transpose + fp16 convert: W[K,N] -> WT[N,K] ----------------
__global__ __launch_bounds__(256) void k_wt(const float* __restrict__ W,
                                            __half* __restrict__ WT, int K, int N) {
    __shared__ float tl[32][33];
    size_t off = (size_t)blockIdx.z * K * N;
    const float* Wp = W + off;
    __half* Tp = WT + off;
    int nb = blockIdx.x * 32, kb = blockIdx.y * 32;
    int tx = threadIdx.x & 31, ty = threadIdx.x >> 5;
    #pragma unroll
    for (int i = 0; i < 32; i += 8)
        tl[ty + i][tx] = Wp[(size_t)(kb + ty + i) * N + nb + tx];
    __syncthreads();
    #pragma unroll
    for (int i = 0; i < 32; i += 8)
        Tp[(size_t)(nb + ty + i) * K + kb + tx] = __float2half_rn(tl[tx][ty + i]);
}

// ---------------- compact block-diag QKV weight: [2304][128] per layer ----------------
__global__ __launch_bounds__(256) void k_wqkv(const float* __restrict__ Wq,
                                              const float* __restrict__ Wk,
                                              const float* __restrict__ Wv,
                                              __half* __restrict__ out) {
    int l = blockIdx.z;
    int i = blockIdx.x * 256 + threadIdx.x;       // over QKV_N * 128
    if (i >= QKV_N * 128) return;
    int n = i >> 7, kp = i & 127;
    int part = n / D_, nn = n % D_;
    int h = nn >> 6, e = nn & 63;
    int hp = h & 1;
    const float* W = ((part == 0) ? Wq : (part == 1) ? Wk : Wv) + (size_t)l * H_ * DH_ * DH_;
    int d = kp - hp * 64;
    float v = (d >= 0 && d < 64) ? W[(size_t)(h * DH_ + d) * DH_ + e] : 0.f;
    out[(size_t)l * QKV_N * 128 + i] = __float2half_rn(v);
}

// ---------------- sinusoidal PE table ----------------
__global__ void k_pe() {
    int i = blockIdx.x * 256 + threadIdx.x;
    if (i >= S_ * D_) return;
    int s = i / D_, d = i % D_;
    int p2 = d & ~1;
    float freq = expf(-(float)p2 * (9.210340371976184f / (float)D_));
    float ang = (float)s * freq;
    g_pe[i] = (d & 1) ? cosf(ang) : sinf(ang);
}

// ---------------- embedding + PE ----------------
__global__ void k_embed(const int* __restrict__ tokens, const float* __restrict__ emb) {
    int row = blockIdx.x;
    int s = row & (S_ - 1);
    int tok = tokens[row];
    for (int d = threadIdx.x; d < D_; d += blockDim.x)
        g_x[row * D_ + d] = emb[tok * D_ + d] + g_pe[s * D_ + d];
}

// ---------------- action embedding gather ----------------
__global__ void k_act(const int* __restrict__ actions, const float* __restrict__ act_emb) {
    int i = blockIdx.x * blockDim.x + threadIdx.x;
    if (i >= B_ * COND_) return;
    int b = i / COND_, c = i % COND_;
    int n = c / DPA_, j = c % DPA_;
    g_a[i] = act_emb[actions[b * NACT_ + n] * DPA_ + j];
}

// ---------------- all conditional gain/shift vectors in one launch ----------------
__global__ __launch_bounds__(256) void k_condvec_all(const float* __restrict__ ln1_g,
                                                     const float* __restrict__ ln1_b,
                                                     const float* __restrict__ ln2_g,
                                                     const float* __restrict__ ln2_b,
                                                     const float* __restrict__ lnf_g,
                                                     const float* __restrict__ lnf_b) {
    int slot = blockIdx.y;
    const float *gw, *bw;
    if (slot < L_)            { size_t o = (size_t)slot * COND_ * D_;        gw = ln1_g + o; bw = ln1_b + o; }
    else if (slot < 2 * L_)   { size_t o = (size_t)(slot - L_) * COND_ * D_; gw = ln2_g + o; bw = ln2_b + o; }
    else                      { gw = lnf_g; bw = lnf_b; }
    int i = blockIdx.x * 256 + threadIdx.x;
    if (i >= B_ * D_) return;
    int b = i / D_, d = i % D_;
    const float* ar = g_a + b * COND_;
    float sg = 0.f, sb = 0.f;
    for (int c = 0; c < COND_; c++) {
        float av = ar[c];
        sg += av * gw[c * D_ + d];
        sb += av * bw[c * D_ + d];
    }
    g_gvA[(size_t)slot * B_ * D_ + i] = sg;
    g_bvA[(size_t)slot * B_ * D_ + i] = sb;
}

// ---------------- conditional layernorm: g_x -> g_hh (fp16) ----------------
__global__ __launch_bounds__(256) void k_condln(int slot) {
    int row = blockIdx.x;
    int b = row >> 10;
    const float* xp = g_x + row * D_;
    int t = threadIdx.x;
    float x0 = xp[t], x1 = xp[t + 256], x2 = xp[t + 512];
    float s1 = x0 + x1 + x2;
    float s2 = x0 * x0 + x1 * x1 + x2 * x2;
    #pragma unroll
    for (int o = 16; o; o >>= 1) {
        s1 += __shfl_xor_sync(0xffffffffu, s1, o);
        s2 += __shfl_xor_sync(0xffffffffu, s2, o);
    }
    __shared__ float rs1[8], rs2[8];
    __shared__ float mu_s, rstd_s;
    int w = t >> 5;
    if ((t & 31) == 0) { rs1[w] = s1; rs2[w] = s2; }
    __syncthreads();
    if (t == 0) {
        float a1 = 0.f, a2 = 0.f;
        #pragma unroll
        for (int i = 0; i < 8; i++) { a1 += rs1[i]; a2 += rs2[i]; }
        float mu = a1 / (float)D_;
        float var = a2 / (float)D_ - mu * mu;
        mu_s = mu;
        rstd_s = rsqrtf(var + 1e-5f);
    }
    __syncthreads();
    float mu = mu_s, rstd = rstd_s;
    const float* gv = g_gvA + (size_t)slot * B_ * D_ + b * D_;
    const float* bv = g_bvA + (size_t)slot * B_ * D_ + b * D_;
    __half* hp = g_hh + (size_t)row * D_;
    hp[t]       = __float2half_rn((x0 - mu) * rstd * gv[t]       + bv[t]);
    hp[t + 256] = __float2half_rn((x1 - mu) * rstd * gv[t + 256] + bv[t + 256]);
    hp[t + 512] = __float2half_rn((x2 - mu) * rstd * gv[t + 512] + bv[t + 512]);
}

// ---------------- tensor-core flash attention ----------------
__global__ __launch_bounds__(256) void k_flash_tc() {
    extern __shared__ char fsm[];
    uint32_t sb = smem_u32(fsm);
    int t = threadIdx.x, lane = t & 31, wid = t >> 5;
    int bh = blockIdx.y;
    int b = bh / H_, h = bh % H_;
    int qBase = blockIdx.x * 128;
    int qr = lane >> 2, qc = lane & 3;

    const __half* qg = g_qkv + (size_t)(b * S_ + qBase) * QKV_N + h * DH_;
    #pragma unroll
    for (int i = 0; i < 4; i++) {
        int id = t + i * 256;
        int r = id >> 3, c8 = id & 7;
        cp16(sb + (uint32_t)(r * 128 + ((c8 ^ (r & 7)) << 4)), qg + (size_t)r * QKV_N + c8 * 8);
    }
    auto issueKV = [&](int kt, int s) {
        uint32_t st = sb + 16384u + (uint32_t)s * 16384u;
        const __half* kg = g_qkv + (size_t)(b * S_ + kt) * QKV_N + D_ + h * DH_;
        const __half* vg = kg + D_;
        #pragma unroll
        for (int i = 0; i < 2; i++) {
            int id = t + i * 256;
            int r = id >> 3, c8 = id & 7;
            cp16(st + (uint32_t)(r * 128 + ((c8 ^ (r & 7)) << 4)), kg + (size_t)r * QKV_N + c8 * 8);
        }
        #pragma unroll
        for (int i = 0; i < 2; i++) {
            int id = t + i * 256;
            int r = id >> 3, c8 = id & 7;
            cp16(st + 8192u + (uint32_t)(r * 128 + ((c8 ^ (r & 7)) << 4)), vg + (size_t)r * QKV_N + c8 * 8);
        }
        cp_commit();
    };
    issueKV(0, 0);

    uint32_t qa[4][4];
    float sfr[8][4];
    float o[8][4];
    #pragma unroll
    for (int j = 0; j < 8; j++)
        #pragma unroll
        for (int c = 0; c < 4; c++) o[j][c] = 0.f;
    float m_lo = -1e30f, m_hi = -1e30f, l_lo = 0.f, l_hi = 0.f;

    const int nT = S_ / 64;
    for (int tt = 0; tt < nT; tt++) {
        int st = tt & 1;
        if (tt + 1 < nT) { issueKV((tt + 1) * 64, st ^ 1); cp_wait<1>(); }
        else             { cp_wait<0>(); }
        __syncthreads();
        if (tt == 0) {
            const __half2 sc2 = __float2half2_rn(0.1803368801f);   // 0.125*log2(e)
            #pragma unroll
            for (int ks = 0; ks < 4; ks++) {
                int r = wid * 16 + (lane & 15);
                int chunk = ks * 2 + (lane >> 4);
                ldm_x4(qa[ks], sb + (uint32_t)(r * 128 + ((chunk ^ (r & 7)) << 4)));
                #pragma unroll
                for (int j = 0; j < 4; j++) {
                    __half2 hv = *(__half2*)&qa[ks][j];
                    hv = __hmul2(hv, sc2);
                    qa[ks][j] = *(uint32_t*)&hv;
                }
            }
        }
        uint32_t kBase = sb + 16384u + (uint32_t)st * 16384u;
        uint32_t vBase = kBase + 8192u;

        #pragma unroll
        for (int j = 0; j < 8; j++)
            #pragma unroll
            for (int c = 0; c < 4; c++) sfr[j][c] = 0.f;
        {
            int g2 = lane >> 3;
            int rowB = ((g2 >> 1) << 3) + (lane & 7);
            int kb = g2 & 1;
            #pragma unroll
            for (int ks = 0; ks < 4; ks++) {
                #pragma unroll
                for (int nh = 0; nh < 4; nh++) {
                    int r = nh * 16 + rowB;
                    int chunk = ks * 2 + kb;
                    uint32_t q4[4];
                    ldm_x4(q4, kBase + (uint32_t)(r * 128 + ((chunk ^ (r & 7)) << 4)));
                    uint32_t b0[2] = { q4[0], q4[1] };
                    uint32_t b1[2] = { q4[2], q4[3] };
                    mma16816(sfr[nh * 2],     qa[ks], b0);
                    mma16816(sfr[nh * 2 + 1], qa[ks], b1);
                }
            }
        }
        float tl = sfr[0][0], th = sfr[0][2];
        #pragma unroll
        for (int j = 0; j < 8; j++) {
            tl = fmaxf(tl, fmaxf(sfr[j][0], sfr[j][1]));
            th = fmaxf(th, fmaxf(sfr[j][2], sfr[j][3]));
        }
        tl = fmaxf(tl, __shfl_xor_sync(0xffffffffu, tl, 1));
        tl = fmaxf(tl, __shfl_xor_sync(0xffffffffu, tl, 2));
        th = fmaxf(th, __shfl_xor_sync(0xffffffffu, th, 1));
        th = fmaxf(th, __shfl_xor_sync(0xffffffffu, th, 2));
        float mn_lo = fmaxf(m_lo, tl), mn_hi = fmaxf(m_hi, th);
        float corr_lo = exp2f(m_lo - mn_lo), corr_hi = exp2f(m_hi - mn_hi);
        uint32_t ph[8][2];
        float ps_lo = 0.f, ps_hi = 0.f;
        #pragma unroll
        for (int j = 0; j < 8; j++) {
            __half2 e0h = __floats2half2_rn(sfr[j][0] - mn_lo, sfr[j][1] - mn_lo);
            __half2 e1h = __floats2half2_rn(sfr[j][2] - mn_hi, sfr[j][3] - mn_hi);
            ph[j][0] = h2exp2_bits(e0h);
            ph[j][1] = h2exp2_bits(e1h);
            float2 f0 = __half22float2(*(__half2*)&ph[j][0]);
            float2 f1 = __half22float2(*(__half2*)&ph[j][1]);
            ps_lo += f0.x + f0.y;
            ps_hi += f1.x + f1.y;
        }
        l_lo = l_lo * corr_lo + ps_lo;
        l_hi = l_hi * corr_hi + ps_hi;
        m_lo = mn_lo; m_hi = mn_hi;
        #pragma unroll
        for (int j = 0; j < 8; j++) {
            o[j][0] *= corr_lo; o[j][1] *= corr_lo;
            o[j][2] *= corr_hi; o[j][3] *= corr_hi;
        }
        #pragma unroll
        for (int ks = 0; ks < 4; ks++) {
            uint32_t pa[4] = { ph[2 * ks][0], ph[2 * ks][1], ph[2 * ks + 1][0], ph[2 * ks + 1][1] };
            #pragma unroll
            for (int jp = 0; jp < 4; jp++) {
                int r = ks * 16 + (lane & 15);
                int chunk = jp * 2 + (lane >> 4);
                uint32_t q4[4];
                ldm_x4_t(q4, vBase + (uint32_t)(r * 128 + ((chunk ^ (r & 7)) << 4)));
                uint32_t b0[2] = { q4[0], q4[1] };
                uint32_t b1[2] = { q4[2], q4[3] };
                mma16816(o[2 * jp],     pa, b0);
                mma16816(o[2 * jp + 1], pa, b1);
            }
        }
        __syncthreads();
    }
    l_lo += __shfl_xor_sync(0xffffffffu, l_lo, 1);
    l_lo += __shfl_xor_sync(0xffffffffu, l_lo, 2);
    l_hi += __shfl_xor_sync(0xffffffffu, l_hi, 1);
    l_hi += __shfl_xor_sync(0xffffffffu, l_hi, 2);
    float inv_lo = 1.f / l_lo, inv_hi = 1.f / l_hi;
    int rlo = b * S_ + qBase + wid * 16 + qr;
    #pragma unroll
    for (int j = 0; j < 8; j++) {
        int col = h * DH_ + j * 8 + qc * 2;
        *(__half2*)(g_oh + (size_t)rlo * D_ + col) =
            __floats2half2_rn(o[j][0] * inv_lo, o[j][1] * inv_lo);
        *(__half2*)(g_oh + (size_t)(rlo + 8) * D_ + col) =
            __floats2half2_rn(o[j][2] * inv_hi, o[j][3] * inv_hi);
    }
}

// ---------------- fp16 mma.sync GEMM, 3-stage pipeline ----------------
// C[M,N] = epi(A[M,K_eff] @ Bt[N,K_eff]^T); A row stride = lda.
// qkvMode: per-tile A column offset = colBase % 768 (block-diag compact weight).
// epi: 0 = +bias -> fp32 Cf; 1 = gelu(+bias) -> fp16 Ch; 2 = +bias+res -> fp32 Cf; 3 = plain -> fp16 Ch
__global__ __launch_bounds__(256) void k_gemm_mma(const __half* __restrict__ A,
                                                  const __half* __restrict__ Bt,
                                                  const float* __restrict__ bias,
                                                  const float* __restrict__ res,
                                                  float* __restrict__ Cf,
                                                  __half* __restrict__ Ch,
                                                  int M, int N, int K, int lda,
                                                  int epi, int qkvMode) {
    extern __shared__ char smem[];
    uint32_t sb = smem_u32(smem);
    int t = threadIdx.x;
    int lane = t & 31, wid = t >> 5;
    int warpM = wid >> 2, warpN = wid & 3;
    int rowBase = blockIdx.y * BM, colBase = blockIdx.x * BN;
    int kOff = qkvMode ? (colBase % D_) : 0;
    const __half* Ag = A + (size_t)rowBase * lda + kOff;
    const __half* Bg = Bt + (size_t)colBase * K;
    const int nCh = K >> 6;

    float acc[4][4][4];
    #pragma unroll
    for (int i = 0; i < 4; i++)
        #pragma unroll
        for (int j = 0; j < 4; j++)
            #pragma unroll
            for (int c = 0; c < 4; c++) acc[i][j][c] = 0.f;

    auto issue = [&](int ch) {
        uint32_t stage = sb + (uint32_t)(ch % NST) * STAGE_BYTES;
        int kt = ch << 6;
        #pragma unroll
        for (int i = 0; i < 4; i++) {
            int id = t + i * 256;
            int r = id >> 3, c = id & 7;
            cp16(stage + (uint32_t)(r * 128 + ((c ^ (r & 7)) << 4)), Ag + (size_t)r * lda + kt + c * 8);
        }
        #pragma unroll
        for (int i = 0; i < 4; i++) {
            int id = t + i * 256;
            int r = id >> 3, c = id & 7;
            cp16(stage + 16384u + (uint32_t)(r * 128 + ((c ^ (r & 7)) << 4)), Bg + (size_t)r * K + kt + c * 8);
        }
        cp_commit();
    };

    issue(0);
    if (nCh > 1) issue(1);
    for (int ch = 0; ch < nCh; ch++) {
        if (ch + 2 < nCh) { issue(ch + 2); cp_wait<2>(); }
        else if (ch + 1 < nCh) cp_wait<1>();
        else cp_wait<0>();
        __syncthreads();

        uint32_t aBase = sb + (uint32_t)(ch % NST) * STAGE_BYTES;
        uint32_t bBase = aBase + 16384u;
        int lrA = lane & 15, kbA = lane >> 4;
        int g2 = lane >> 3;
        int rowOffB = ((g2 >> 1) << 3) + (lane & 7);
        int kbB = g2 & 1;
        #pragma unroll
        for (int ks = 0; ks < 4; ks++) {
            uint32_t af[4][4];
            int chunkA = ks * 2 + kbA;
            #pragma unroll
            for (int mi = 0; mi < 4; mi++) {
                int r = warpM * 64 + mi * 16 + lrA;
                ldm_x4(af[mi], aBase + (uint32_t)(r * 128 + ((chunkA ^ (r & 7)) << 4)));
            }
            uint32_t bf[4][2];
            int chunkB = ks * 2 + kbB;
            #pragma unroll
            for (int nh = 0; nh < 2; nh++) {
                int r = warpN * 32 + nh * 16 + rowOffB;
                uint32_t q[4];
                ldm_x4(q, bBase + (uint32_t)(r * 128 + ((chunkB ^ (r & 7)) << 4)));
                bf[nh * 2][0] = q[0];     bf[nh * 2][1] = q[1];
                bf[nh * 2 + 1][0] = q[2]; bf[nh * 2 + 1][1] = q[3];
            }
            #pragma unroll
            for (int mi = 0; mi < 4; mi++)
                #pragma unroll
                for (int ni = 0; ni < 4; ni++)
                    mma16816(acc[mi][ni], af[mi], bf[ni]);
        }
        __syncthreads();
    }

    int qr = lane >> 2, qc = lane & 3;
    #pragma unroll
    for (int mi = 0; mi < 4; mi++) {
        #pragma unroll
        for (int ni = 0; ni < 4; ni++) {
            int row0 = rowBase + warpM * 64 + mi * 16 + qr;
            int col  = colBase + warpN * 32 + ni * 8 + qc * 2;
            #pragma unroll
            for (int hrow = 0; hrow < 2; hrow++) {
                int rr = row0 + hrow * 8;
                float v0 = acc[mi][ni][hrow * 2];
                float v1 = acc[mi][ni][hrow * 2 + 1];
                if (epi == 0 || epi == 2) {
                    v0 += bias[col]; v1 += bias[col + 1];
                    if (epi == 2) {
                        const float* rp = res + (size_t)rr * N + col;
                        v0 += rp[0]; v1 += rp[1];
                    }
                    float2 ov; ov.x = v0; ov.y = v1;
                    *(float2*)(Cf + (size_t)rr * N + col) = ov;
                } else if (epi == 1) {
                    v0 = gelu_f(v0 + bias[col]);
                    v1 = gelu_f(v1 + bias[col + 1]);
                    *(__half2*)(Ch + (size_t)rr * N + col) = __floats2half2_rn(v0, v1);
                } else {
                    *(__half2*)(Ch + (size_t)rr * N + col) = __floats2half2_rn(v0, v1);
                }
            }
        }
    }
}

// ---------------- launch sequence ----------------
extern "C" void kernel_launch(void* const* d_in, const int* in_sizes, int n_in,
                              void* d_out, int out_size) {
    const int*   tokens  = (const int*)d_in[0];
    const int*   actions = (const int*)d_in[1];
    const float* emb     = (const float*)d_in[2];
    const float* act_emb = (const float*)d_in[3];
    const float* ln1_g   = (const float*)d_in[4];
    const float* ln1_b   = (const float*)d_in[5];
    const float* Wq      = (const float*)d_in[6];
    const float* Wk      = (const float*)d_in[7];
    const float* Wv      = (const float*)d_in[8];
    const float* Wo      = (const float*)d_in[9];
    const float* bo      = (const float*)d_in[10];
    const float* ln2_g   = (const float*)d_in[11];
    const float* ln2_b   = (const float*)d_in[12];
    const float* W1      = (const float*)d_in[13];
    const float* b1      = (const float*)d_in[14];
    const float* W2      = (const float*)d_in[15];
    const float* b2      = (const float*)d_in[16];
    const float* lnf_g   = (const float*)d_in[17];
    const float* lnf_b   = (const float*)d_in[18];
    const float* Wout    = (const float*)d_in[19];
    const float* bout    = (const float*)d_in[20];

    float *xp;
    __half *hhp, *qkvp, *ohp, *ffp, *wqkvC, *woT, *w1T, *w2T, *woutT;
    cudaGetSymbolAddress((void**)&xp,    g_x);
    cudaGetSymbolAddress((void**)&hhp,   g_hh);
    cudaGetSymbolAddress((void**)&qkvp,  g_qkv);
    cudaGetSymbolAddress((void**)&ohp,   g_oh);
    cudaGetSymbolAddress((void**)&ffp,   g_ffh);
    cudaGetSymbolAddress((void**)&wqkvC, g_WqkvC);
    cudaGetSymbolAddress((void**)&woT,   g_WoT);
    cudaGetSymbolAddress((void**)&w1T,   g_W1T);
    cudaGetSymbolAddress((void**)&w2T,   g_W2T);
    cudaGetSymbolAddress((void**)&woutT, g_WoutT);

    cudaFuncSetAttribute(k_flash_tc, cudaFuncAttributeMaxDynamicSharedMemorySize, FL_SMEM);
    cudaFuncSetAttribute(k_gemm_mma, cudaFuncAttributeMaxDynamicSharedMemorySize, GEMM_SMEM);

    // ---- prep phase (batched) ----
    k_wt<<<dim3(D_ / 32, D_ / 32, L_), 256>>>(Wo, woT, D_, D_);
    k_wt<<<dim3(4 * D_ / 32, D_ / 32, L_), 256>>>(W1, w1T, D_, 4 * D_);
    k_wt<<<dim3(D_ / 32, 4 * D_ / 32, L_), 256>>>(W2, w2T, 4 * D_, D_);
    k_wt<<<dim3(V_ / 32, D_ / 32, 1), 256>>>(Wout, woutT, D_, V_);
    k_wqkv<<<dim3((QKV_N * 128 + 255) / 256, 1, L_), 256>>>(Wq, Wk, Wv, wqkvC);
    k_pe<<<(S_ * D_ + 255) / 256, 256>>>();
    k_embed<<<BS_, 256>>>(tokens, emb);
    k_act<<<(B_ * COND_ + 255) / 256, 256>>>(actions, act_emb);
    k_condvec_all<<<dim3((B_ * D_ + 255) / 256, NSLOT), 256>>>(ln1_g, ln1_b, ln2_g, ln2_b, lnf_g, lnf_b);

    // ---- layers ----
    for (int l = 0; l < L_; l++) {
        k_condln<<<BS_, 256>>>(l);
        // fused block-diag qkv, compact K=128
        k_gemm_mma<<<dim3(QKV_N / BN, BS_ / BM), 256, GEMM_SMEM>>>(
            hhp, wqkvC + (size_t)l * QKV_N * 128, nullptr, nullptr, nullptr, qkvp,
            BS_, QKV_N, 128, D_, 3, 1);
        k_flash_tc<<<dim3(S_ / 128, B_ * H_), 256, FL_SMEM>>>();
        k_gemm_mma<<<dim3(D_ / BN, BS_ / BM), 256, GEMM_SMEM>>>(
            ohp, woT + (size_t)l * D_ * D_, bo + l * D_, xp, xp, nullptr,
            BS_, D_, D_, D_, 2, 0);
        k_condln<<<BS_, 256>>>(L_ + l);
        k_gemm_mma<<<dim3(4 * D_ / BN, BS_ / BM), 256, GEMM_SMEM>>>(
            hhp, w1T + (size_t)l * 4 * D_ * D_, b1 + l * 4 * D_, nullptr, nullptr, ffp,
            BS_, 4 * D_, D_, D_, 1, 0);
        k_gemm_mma<<<dim3(D_ / BN, BS_ / BM), 256, GEMM_SMEM>>>(
            ffp, w2T + (size_t)l * D_ * 4 * D_, b2 + l * D_, xp, xp, nullptr,
            BS_, D_, 4 * D_, 4 * D_, 2, 0);
    }
    k_condln<<<BS_, 256>>>(2 * L_);
    k_gemm_mma<<<dim3(V_ / BN, BS_ / BM), 256, GEMM_SMEM>>>(
        hhp, woutT, bout, nullptr, (float*)d_out, nullptr,
        BS_, V_, D_, D_, 0, 0);
}

// round 7
// speedup vs baseline: 14.1568x; 1.0177x over previous
#include <cuda_runtime.h>
#include <cuda_fp16.h>
#include <math.h>
#include <stdint.h>

// ---------------- constants ----------------
namespace {
constexpr int B_ = 8, S_ = 1024, D_ = 768, H_ = 12, DH_ = 64, V_ = 1024;
constexpr int L_ = 8;
constexpr int COND_ = 256, NACT_ = 4, DPA_ = 64;
constexpr int BS_ = B_ * S_;               // 8192
constexpr int QKV_N = 3 * D_;              // 2304
constexpr int NSLOT = 2 * L_ + 1;          // 17 cond-LN slots
// mma.sync GEMM tiling
constexpr int BM = 128, BN = 128;
constexpr int STAGE_BYTES = 32768;         // A 16KB + B 16KB per stage
constexpr int NST = 3;
constexpr int GEMM_SMEM = NST * STAGE_BYTES; // 96KB, 3-stage
// flash tiling
constexpr int FL_SMEM = 16384 + 2 * 16384; // Q 16KB + 2 stages of (K 8KB + V 8KB)
}

// ---------------- scratch (static device globals; no runtime alloc) ----------------
__device__ float  g_x  [BS_ * D_];
__device__ float  g_pe [S_ * D_];
__device__ __half g_hh [BS_ * D_];
__device__ __half g_qkv[BS_ * QKV_N];
__device__ __half g_oh [BS_ * D_];
__device__ __half g_ffh[BS_ * 4 * D_];
__device__ float  g_a  [B_ * COND_];
__device__ float  g_gvA[NSLOT * B_ * D_];
__device__ float  g_bvA[NSLOT * B_ * D_];
__device__ __half g_WqkvC[L_ * QKV_N * 128];   // compact block-diag, [N][128]
__device__ __half g_WoT  [L_ * D_ * D_];
__device__ __half g_W1T  [L_ * 4 * D_ * D_];
__device__ __half g_W2T  [L_ * D_ * 4 * D_];
__device__ __half g_WoutT[V_ * D_];

// ---------------- small helpers ----------------
__device__ __forceinline__ uint32_t smem_u32(const void* p) {
    uint32_t a;
    asm("{ .reg .u64 t; cvta.to.shared.u64 t, %1; cvt.u32.u64 %0, t; }" : "=r"(a) : "l"(p));
    return a;
}
__device__ __forceinline__ void cp16(uint32_t dst, const void* src) {
    asm volatile("cp.async.cg.shared.global [%0], [%1], 16;" :: "r"(dst), "l"(src) : "memory");
}
__device__ __forceinline__ void cp_commit() {
    asm volatile("cp.async.commit_group;" ::: "memory");
}
template <int N> __device__ __forceinline__ void cp_wait() {
    asm volatile("cp.async.wait_group %0;" :: "n"(N) : "memory");
}
__device__ __forceinline__ void ldm_x4(uint32_t* r, uint32_t addr) {
    asm volatile("ldmatrix.sync.aligned.m8n8.x4.shared.b16 {%0,%1,%2,%3}, [%4];"
                 : "=r"(r[0]), "=r"(r[1]), "=r"(r[2]), "=r"(r[3]) : "r"(addr));
}
__device__ __forceinline__ void ldm_x4_t(uint32_t* r, uint32_t addr) {
    asm volatile("ldmatrix.sync.aligned.m8n8.x4.trans.shared.b16 {%0,%1,%2,%3}, [%4];"
                 : "=r"(r[0]), "=r"(r[1]), "=r"(r[2]), "=r"(r[3]) : "r"(addr));
}
__device__ __forceinline__ void mma16816(float* c, const uint32_t* a, const uint32_t* b) {
    asm volatile("mma.sync.aligned.m16n8k16.row.col.f32.f16.f16.f32 "
                 "{%0,%1,%2,%3}, {%4,%5,%6,%7}, {%8,%9}, {%0,%1,%2,%3};"
                 : "+f"(c[0]), "+f"(c[1]), "+f"(c[2]), "+f"(c[3])
                 : "r"(a[0]), "r"(a[1]), "r"(a[2]), "r"(a[3]), "r"(b[0]), "r"(b[1]));
}
__device__ __forceinline__ uint32_t h2exp2_bits(__half2 x) {
    uint32_t y;
    asm("ex2.approx.f16x2 %0, %1;" : "=r"(y) : "r"(*(uint32_t*)&x));
    return y;
}
__device__ __forceinline__ float gelu_f(float x) {
    float x3 = x * x * x;
    return 0.5f * x * (1.f + tanhf(0.7978845608028654f * (x + 0.044715f * x3)));
}

// ---------------- batched weight transpose + fp16 convert: W[K,N] -> WT[N,K] ----------------
__global__ __launch_bounds__(256) void k_wt(const float* __restrict__ W,
                                            __half* __restrict__ WT, int K, int N) {
    __shared__ float tl[32][33];
    size_t off = (size_t)blockIdx.z * K * N;
    const float* Wp = W + off;
    __half* Tp = WT + off;
    int nb = blockIdx.x * 32, kb = blockIdx.y * 32;
    int tx = threadIdx.x & 31, ty = threadIdx.x >> 5;
    #pragma unroll
    for (int i = 0; i < 32; i += 8)
        tl[ty + i][tx] = Wp[(size_t)(kb + ty + i) * N + nb + tx];
    __syncthreads();
    #pragma unroll
    for (int i = 0; i < 32; i += 8)
        Tp[(size_t)(nb + ty + i) * K + kb + tx] = __float2half_rn(tl[tx][ty + i]);
}

// ---------------- compact block-diag QKV weight: [2304][128] per layer ----------------
__global__ __launch_bounds__(256) void k_wqkv(const float* __restrict__ Wq,
                                              const float* __restrict__ Wk,
                                              const float* __restrict__ Wv,
                                              __half* __restrict__ out) {
    int l = blockIdx.z;
    int i = blockIdx.x * 256 + threadIdx.x;
    if (i >= QKV_N * 128) return;
    int n = i >> 7, kp = i & 127;
    int part = n / D_, nn = n % D_;
    int h = nn >> 6, e = nn & 63;
    int hp = h & 1;
    const float* W = ((part == 0) ? Wq : (part == 1) ? Wk : Wv) + (size_t)l * H_ * DH_ * DH_;
    int d = kp - hp * 64;
    float v = (d >= 0 && d < 64) ? W[(size_t)(h * DH_ + d) * DH_ + e] : 0.f;
    out[(size_t)l * QKV_N * 128 + i] = __float2half_rn(v);
}

// ---------------- sinusoidal PE table ----------------
__global__ void k_pe() {
    int i = blockIdx.x * 256 + threadIdx.x;
    if (i >= S_ * D_) return;
    int s = i / D_, d = i % D_;
    int p2 = d & ~1;
    float freq = expf(-(float)p2 * (9.210340371976184f / (float)D_));
    float ang = (float)s * freq;
    g_pe[i] = (d & 1) ? cosf(ang) : sinf(ang);
}

// ---------------- embedding + PE ----------------
__global__ void k_embed(const int* __restrict__ tokens, const float* __restrict__ emb) {
    int row = blockIdx.x;
    int s = row & (S_ - 1);
    int tok = tokens[row];
    for (int d = threadIdx.x; d < D_; d += blockDim.x)
        g_x[row * D_ + d] = emb[tok * D_ + d] + g_pe[s * D_ + d];
}

// ---------------- action embedding gather ----------------
__global__ void k_act(const int* __restrict__ actions, const float* __restrict__ act_emb) {
    int i = blockIdx.x * blockDim.x + threadIdx.x;
    if (i >= B_ * COND_) return;
    int b = i / COND_, c = i % COND_;
    int n = c / DPA_, j = c % DPA_;
    g_a[i] = act_emb[actions[b * NACT_ + n] * DPA_ + j];
}

// ---------------- all conditional gain/shift vectors in one launch ----------------
__global__ __launch_bounds__(256) void k_condvec_all(const float* __restrict__ ln1_g,
                                                     const float* __restrict__ ln1_b,
                                                     const float* __restrict__ ln2_g,
                                                     const float* __restrict__ ln2_b,
                                                     const float* __restrict__ lnf_g,
                                                     const float* __restrict__ lnf_b) {
    int slot = blockIdx.y;
    const float *gw, *bw;
    if (slot < L_)            { size_t o = (size_t)slot * COND_ * D_;        gw = ln1_g + o; bw = ln1_b + o; }
    else if (slot < 2 * L_)   { size_t o = (size_t)(slot - L_) * COND_ * D_; gw = ln2_g + o; bw = ln2_b + o; }
    else                      { gw = lnf_g; bw = lnf_b; }
    int i = blockIdx.x * 256 + threadIdx.x;
    if (i >= B_ * D_) return;
    int b = i / D_, d = i % D_;
    const float* ar = g_a + b * COND_;
    float sg = 0.f, sb = 0.f;
    for (int c = 0; c < COND_; c++) {
        float av = ar[c];
        sg += av * gw[c * D_ + d];
        sb += av * bw[c * D_ + d];
    }
    g_gvA[(size_t)slot * B_ * D_ + i] = sg;
    g_bvA[(size_t)slot * B_ * D_ + i] = sb;
}

// ---------------- conditional layernorm (vectorized): g_x -> g_hh (fp16) ----------------
// 192 threads, one float4 per thread (D = 768 = 192*4)
__global__ __launch_bounds__(192) void k_condln(int slot) {
    int row = blockIdx.x;
    int b = row >> 10;
    int t = threadIdx.x;
    const float4* xp = (const float4*)(g_x + (size_t)row * D_);
    float4 x = xp[t];
    float s1 = x.x + x.y + x.z + x.w;
    float s2 = x.x * x.x + x.y * x.y + x.z * x.z + x.w * x.w;
    #pragma unroll
    for (int o = 16; o; o >>= 1) {
        s1 += __shfl_xor_sync(0xffffffffu, s1, o);
        s2 += __shfl_xor_sync(0xffffffffu, s2, o);
    }
    __shared__ float rs1[6], rs2[6];
    __shared__ float mu_s, rstd_s;
    int w = t >> 5;
    if ((t & 31) == 0) { rs1[w] = s1; rs2[w] = s2; }
    __syncthreads();
    if (t == 0) {
        float a1 = 0.f, a2 = 0.f;
        #pragma unroll
        for (int i = 0; i < 6; i++) { a1 += rs1[i]; a2 += rs2[i]; }
        float mu = a1 / (float)D_;
        float var = a2 / (float)D_ - mu * mu;
        mu_s = mu;
        rstd_s = rsqrtf(var + 1e-5f);
    }
    __syncthreads();
    float mu = mu_s, rstd = rstd_s;
    const float4* gv = (const float4*)(g_gvA + (size_t)slot * B_ * D_ + b * D_);
    const float4* bv = (const float4*)(g_bvA + (size_t)slot * B_ * D_ + b * D_);
    float4 g = gv[t], bb = bv[t];
    float v0 = (x.x - mu) * rstd * g.x + bb.x;
    float v1 = (x.y - mu) * rstd * g.y + bb.y;
    float v2 = (x.z - mu) * rstd * g.z + bb.z;
    float v3 = (x.w - mu) * rstd * g.w + bb.w;
    uint2 pk;
    __half2 h01 = __floats2half2_rn(v0, v1);
    __half2 h23 = __floats2half2_rn(v2, v3);
    pk.x = *(uint32_t*)&h01;
    pk.y = *(uint32_t*)&h23;
    *(uint2*)(g_hh + (size_t)row * D_ + t * 4) = pk;
}

// ---------------- tensor-core flash attention (MUFU/MMA interleaved) ----------------
__global__ __launch_bounds__(256) void k_flash_tc() {
    extern __shared__ char fsm[];
    uint32_t sb = smem_u32(fsm);
    int t = threadIdx.x, lane = t & 31, wid = t >> 5;
    int bh = blockIdx.y;
    int b = bh / H_, h = bh % H_;
    int qBase = blockIdx.x * 128;
    int qr = lane >> 2, qc = lane & 3;

    const __half* qg = g_qkv + (size_t)(b * S_ + qBase) * QKV_N + h * DH_;
    #pragma unroll
    for (int i = 0; i < 4; i++) {
        int id = t + i * 256;
        int r = id >> 3, c8 = id & 7;
        cp16(sb + (uint32_t)(r * 128 + ((c8 ^ (r & 7)) << 4)), qg + (size_t)r * QKV_N + c8 * 8);
    }
    auto issueKV = [&](int kt, int s) {
        uint32_t st = sb + 16384u + (uint32_t)s * 16384u;
        const __half* kg = g_qkv + (size_t)(b * S_ + kt) * QKV_N + D_ + h * DH_;
        const __half* vg = kg + D_;
        #pragma unroll
        for (int i = 0; i < 2; i++) {
            int id = t + i * 256;
            int r = id >> 3, c8 = id & 7;
            cp16(st + (uint32_t)(r * 128 + ((c8 ^ (r & 7)) << 4)), kg + (size_t)r * QKV_N + c8 * 8);
        }
        #pragma unroll
        for (int i = 0; i < 2; i++) {
            int id = t + i * 256;
            int r = id >> 3, c8 = id & 7;
            cp16(st + 8192u + (uint32_t)(r * 128 + ((c8 ^ (r & 7)) << 4)), vg + (size_t)r * QKV_N + c8 * 8);
        }
        cp_commit();
    };
    issueKV(0, 0);

    uint32_t qa[4][4];
    float sfr[8][4];
    float o[8][4];
    #pragma unroll
    for (int j = 0; j < 8; j++)
        #pragma unroll
        for (int c = 0; c < 4; c++) o[j][c] = 0.f;
    float m_lo = -1e30f, m_hi = -1e30f, l_lo = 0.f, l_hi = 0.f;

    const int nT = S_ / 64;
    for (int tt = 0; tt < nT; tt++) {
        int st = tt & 1;
        if (tt + 1 < nT) { issueKV((tt + 1) * 64, st ^ 1); cp_wait<1>(); }
        else             { cp_wait<0>(); }
        __syncthreads();
        if (tt == 0) {
            const __half2 sc2 = __float2half2_rn(0.1803368801f);   // 0.125*log2(e)
            #pragma unroll
            for (int ks = 0; ks < 4; ks++) {
                int r = wid * 16 + (lane & 15);
                int chunk = ks * 2 + (lane >> 4);
                ldm_x4(qa[ks], sb + (uint32_t)(r * 128 + ((chunk ^ (r & 7)) << 4)));
                #pragma unroll
                for (int j = 0; j < 4; j++) {
                    __half2 hv = *(__half2*)&qa[ks][j];
                    hv = __hmul2(hv, sc2);
                    qa[ks][j] = *(uint32_t*)&hv;
                }
            }
        }
        uint32_t kBase = sb + 16384u + (uint32_t)st * 16384u;
        uint32_t vBase = kBase + 8192u;

        // ---- S = Qs @ K^T ----
        #pragma unroll
        for (int j = 0; j < 8; j++)
            #pragma unroll
            for (int c = 0; c < 4; c++) sfr[j][c] = 0.f;
        {
            int g2 = lane >> 3;
            int rowB = ((g2 >> 1) << 3) + (lane & 7);
            int kb = g2 & 1;
            #pragma unroll
            for (int ks = 0; ks < 4; ks++) {
                #pragma unroll
                for (int nh = 0; nh < 4; nh++) {
                    int r = nh * 16 + rowB;
                    int chunk = ks * 2 + kb;
                    uint32_t q4[4];
                    ldm_x4(q4, kBase + (uint32_t)(r * 128 + ((chunk ^ (r & 7)) << 4)));
                    uint32_t b0[2] = { q4[0], q4[1] };
                    uint32_t b1[2] = { q4[2], q4[3] };
                    mma16816(sfr[nh * 2],     qa[ks], b0);
                    mma16816(sfr[nh * 2 + 1], qa[ks], b1);
                }
            }
        }
        // ---- row maxes + rescale O (ALU/FMA only, no MUFU bursts) ----
        float tl = sfr[0][0], th = sfr[0][2];
        #pragma unroll
        for (int j = 0; j < 8; j++) {
            tl = fmaxf(tl, fmaxf(sfr[j][0], sfr[j][1]));
            th = fmaxf(th, fmaxf(sfr[j][2], sfr[j][3]));
        }
        tl = fmaxf(tl, __shfl_xor_sync(0xffffffffu, tl, 1));
        tl = fmaxf(tl, __shfl_xor_sync(0xffffffffu, tl, 2));
        th = fmaxf(th, __shfl_xor_sync(0xffffffffu, th, 1));
        th = fmaxf(th, __shfl_xor_sync(0xffffffffu, th, 2));
        float mn_lo = fmaxf(m_lo, tl), mn_hi = fmaxf(m_hi, th);
        float corr_lo = exp2f(m_lo - mn_lo), corr_hi = exp2f(m_hi - mn_hi);
        l_lo *= corr_lo; l_hi *= corr_hi;
        m_lo = mn_lo; m_hi = mn_hi;
        #pragma unroll
        for (int j = 0; j < 8; j++) {
            o[j][0] *= corr_lo; o[j][1] *= corr_lo;
            o[j][2] *= corr_hi; o[j][3] *= corr_hi;
        }
        // ---- interleaved: exp(chunk ks) + PV mma(chunk ks) ----
        float ps_lo = 0.f, ps_hi = 0.f;
        #pragma unroll
        for (int ks = 0; ks < 4; ks++) {
            uint32_t pa[4];
            #pragma unroll
            for (int jj = 0; jj < 2; jj++) {
                int j = 2 * ks + jj;
                __half2 e0h = __floats2half2_rn(sfr[j][0] - mn_lo, sfr[j][1] - mn_lo);
                __half2 e1h = __floats2half2_rn(sfr[j][2] - mn_hi, sfr[j][3] - mn_hi);
                uint32_t p0 = h2exp2_bits(e0h);
                uint32_t p1 = h2exp2_bits(e1h);
                pa[2 * jj] = p0; pa[2 * jj + 1] = p1;
                float2 f0 = __half22float2(*(__half2*)&p0);
                float2 f1 = __half22float2(*(__half2*)&p1);
                ps_lo += f0.x + f0.y;
                ps_hi += f1.x + f1.y;
            }
            #pragma unroll
            for (int jp = 0; jp < 4; jp++) {
                int r = ks * 16 + (lane & 15);
                int chunk = jp * 2 + (lane >> 4);
                uint32_t q4[4];
                ldm_x4_t(q4, vBase + (uint32_t)(r * 128 + ((chunk ^ (r & 7)) << 4)));
                uint32_t b0[2] = { q4[0], q4[1] };
                uint32_t b1[2] = { q4[2], q4[3] };
                mma16816(o[2 * jp],     pa, b0);
                mma16816(o[2 * jp + 1], pa, b1);
            }
        }
        l_lo += ps_lo;
        l_hi += ps_hi;
        __syncthreads();
    }
    l_lo += __shfl_xor_sync(0xffffffffu, l_lo, 1);
    l_lo += __shfl_xor_sync(0xffffffffu, l_lo, 2);
    l_hi += __shfl_xor_sync(0xffffffffu, l_hi, 1);
    l_hi += __shfl_xor_sync(0xffffffffu, l_hi, 2);
    float inv_lo = 1.f / l_lo, inv_hi = 1.f / l_hi;
    int rlo = b * S_ + qBase + wid * 16 + qr;
    #pragma unroll
    for (int j = 0; j < 8; j++) {
        int col = h * DH_ + j * 8 + qc * 2;
        *(__half2*)(g_oh + (size_t)rlo * D_ + col) =
            __floats2half2_rn(o[j][0] * inv_lo, o[j][1] * inv_lo);
        *(__half2*)(g_oh + (size_t)(rlo + 8) * D_ + col) =
            __floats2half2_rn(o[j][2] * inv_hi, o[j][3] * inv_hi);
    }
}

// ---------------- fp16 mma.sync GEMM, 3-stage pipeline ----------------
__global__ __launch_bounds__(256) void k_gemm_mma(const __half* __restrict__ A,
                                                  const __half* __restrict__ Bt,
                                                  const float* __restrict__ bias,
                                                  const float* __restrict__ res,
                                                  float* __restrict__ Cf,
                                                  __half* __restrict__ Ch,
                                                  int M, int N, int K, int lda,
                                                  int epi, int qkvMode) {
    extern __shared__ char smem[];
    uint32_t sb = smem_u32(smem);
    int t = threadIdx.x;
    int lane = t & 31, wid = t >> 5;
    int warpM = wid >> 2, warpN = wid & 3;
    int rowBase = blockIdx.y * BM, colBase = blockIdx.x * BN;
    int kOff = qkvMode ? (colBase % D_) : 0;
    const __half* Ag = A + (size_t)rowBase * lda + kOff;
    const __half* Bg = Bt + (size_t)colBase * K;
    const int nCh = K >> 6;

    float acc[4][4][4];
    #pragma unroll
    for (int i = 0; i < 4; i++)
        #pragma unroll
        for (int j = 0; j < 4; j++)
            #pragma unroll
            for (int c = 0; c < 4; c++) acc[i][j][c] = 0.f;

    auto issue = [&](int ch) {
        uint32_t stage = sb + (uint32_t)(ch % NST) * STAGE_BYTES;
        int kt = ch << 6;
        #pragma unroll
        for (int i = 0; i < 4; i++) {
            int id = t + i * 256;
            int r = id >> 3, c = id & 7;
            cp16(stage + (uint32_t)(r * 128 + ((c ^ (r & 7)) << 4)), Ag + (size_t)r * lda + kt + c * 8);
        }
        #pragma unroll
        for (int i = 0; i < 4; i++) {
            int id = t + i * 256;
            int r = id >> 3, c = id & 7;
            cp16(stage + 16384u + (uint32_t)(r * 128 + ((c ^ (r & 7)) << 4)), Bg + (size_t)r * K + kt + c * 8);
        }
        cp_commit();
    };

    issue(0);
    if (nCh > 1) issue(1);
    for (int ch = 0; ch < nCh; ch++) {
        if (ch + 2 < nCh) { issue(ch + 2); cp_wait<2>(); }
        else if (ch + 1 < nCh) cp_wait<1>();
        else cp_wait<0>();
        __syncthreads();

        uint32_t aBase = sb + (uint32_t)(ch % NST) * STAGE_BYTES;
        uint32_t bBase = aBase + 16384u;
        int lrA = lane & 15, kbA = lane >> 4;
        int g2 = lane >> 3;
        int rowOffB = ((g2 >> 1) << 3) + (lane & 7);
        int kbB = g2 & 1;
        #pragma unroll
        for (int ks = 0; ks < 4; ks++) {
            uint32_t af[4][4];
            int chunkA = ks * 2 + kbA;
            #pragma unroll
            for (int mi = 0; mi < 4; mi++) {
                int r = warpM * 64 + mi * 16 + lrA;
                ldm_x4(af[mi], aBase + (uint32_t)(r * 128 + ((chunkA ^ (r & 7)) << 4)));
            }
            uint32_t bf[4][2];
            int chunkB = ks * 2 + kbB;
            #pragma unroll
            for (int nh = 0; nh < 2; nh++) {
                int r = warpN * 32 + nh * 16 + rowOffB;
                uint32_t q[4];
                ldm_x4(q, bBase + (uint32_t)(r * 128 + ((chunkB ^ (r & 7)) << 4)));
                bf[nh * 2][0] = q[0];     bf[nh * 2][1] = q[1];
                bf[nh * 2 + 1][0] = q[2]; bf[nh * 2 + 1][1] = q[3];
            }
            #pragma unroll
            for (int mi = 0; mi < 4; mi++)
                #pragma unroll
                for (int ni = 0; ni < 4; ni++)
                    mma16816(acc[mi][ni], af[mi], bf[ni]);
        }
        __syncthreads();
    }

    int qr = lane >> 2, qc = lane & 3;
    #pragma unroll
    for (int mi = 0; mi < 4; mi++) {
        #pragma unroll
        for (int ni = 0; ni < 4; ni++) {
            int row0 = rowBase + warpM * 64 + mi * 16 + qr;
            int col  = colBase + warpN * 32 + ni * 8 + qc * 2;
            #pragma unroll
            for (int hrow = 0; hrow < 2; hrow++) {
                int rr = row0 + hrow * 8;
                float v0 = acc[mi][ni][hrow * 2];
                float v1 = acc[mi][ni][hrow * 2 + 1];
                if (epi == 0 || epi == 2) {
                    v0 += bias[col]; v1 += bias[col + 1];
                    if (epi == 2) {
                        const float* rp = res + (size_t)rr * N + col;
                        v0 += rp[0]; v1 += rp[1];
                    }
                    float2 ov; ov.x = v0; ov.y = v1;
                    *(float2*)(Cf + (size_t)rr * N + col) = ov;
                } else if (epi == 1) {
                    v0 = gelu_f(v0 + bias[col]);
                    v1 = gelu_f(v1 + bias[col + 1]);
                    *(__half2*)(Ch + (size_t)rr * N + col) = __floats2half2_rn(v0, v1);
                } else {
                    *(__half2*)(Ch + (size_t)rr * N + col) = __floats2half2_rn(v0, v1);
                }
            }
        }
    }
}

// ---------------- launch sequence ----------------
extern "C" void kernel_launch(void* const* d_in, const int* in_sizes, int n_in,
                              void* d_out, int out_size) {
    const int*   tokens  = (const int*)d_in[0];
    const int*   actions = (const int*)d_in[1];
    const float* emb     = (const float*)d_in[2];
    const float* act_emb = (const float*)d_in[3];
    const float* ln1_g   = (const float*)d_in[4];
    const float* ln1_b   = (const float*)d_in[5];
    const float* Wq      = (const float*)d_in[6];
    const float* Wk      = (const float*)d_in[7];
    const float* Wv      = (const float*)d_in[8];
    const float* Wo      = (const float*)d_in[9];
    const float* bo      = (const float*)d_in[10];
    const float* ln2_g   = (const float*)d_in[11];
    const float* ln2_b   = (const float*)d_in[12];
    const float* W1      = (const float*)d_in[13];
    const float* b1      = (const float*)d_in[14];
    const float* W2      = (const float*)d_in[15];
    const float* b2      = (const float*)d_in[16];
    const float* lnf_g   = (const float*)d_in[17];
    const float* lnf_b   = (const float*)d_in[18];
    const float* Wout    = (const float*)d_in[19];
    const float* bout    = (const float*)d_in[20];

    float *xp;
    __half *hhp, *qkvp, *ohp, *ffp, *wqkvC, *woT, *w1T, *w2T, *woutT;
    cudaGetSymbolAddress((void**)&xp,    g_x);
    cudaGetSymbolAddress((void**)&hhp,   g_hh);
    cudaGetSymbolAddress((void**)&qkvp,  g_qkv);
    cudaGetSymbolAddress((void**)&ohp,   g_oh);
    cudaGetSymbolAddress((void**)&ffp,   g_ffh);
    cudaGetSymbolAddress((void**)&wqkvC, g_WqkvC);
    cudaGetSymbolAddress((void**)&woT,   g_WoT);
    cudaGetSymbolAddress((void**)&w1T,   g_W1T);
    cudaGetSymbolAddress((void**)&w2T,   g_W2T);
    cudaGetSymbolAddress((void**)&woutT, g_WoutT);

    cudaFuncSetAttribute(k_flash_tc, cudaFuncAttributeMaxDynamicSharedMemorySize, FL_SMEM);
    cudaFuncSetAttribute(k_gemm_mma, cudaFuncAttributeMaxDynamicSharedMemorySize, GEMM_SMEM);

    // ---- prep phase (batched) ----
    k_wt<<<dim3(D_ / 32, D_ / 32, L_), 256>>>(Wo, woT, D_, D_);
    k_wt<<<dim3(4 * D_ / 32, D_ / 32, L_), 256>>>(W1, w1T, D_, 4 * D_);
    k_wt<<<dim3(D_ / 32, 4 * D_ / 32, L_), 256>>>(W2, w2T, 4 * D_, D_);
    k_wt<<<dim3(V_ / 32, D_ / 32, 1), 256>>>(Wout, woutT, D_, V_);
    k_wqkv<<<dim3((QKV_N * 128 + 255) / 256, 1, L_), 256>>>(Wq, Wk, Wv, wqkvC);
    k_pe<<<(S_ * D_ + 255) / 256, 256>>>();
    k_embed<<<BS_, 256>>>(tokens, emb);
    k_act<<<(B_ * COND_ + 255) / 256, 256>>>(actions, act_emb);
    k_condvec_all<<<dim3((B_ * D_ + 255) / 256, NSLOT), 256>>>(ln1_g, ln1_b, ln2_g, ln2_b, lnf_g, lnf_b);

    // ---- layers ----
    for (int l = 0; l < L_; l++) {
        k_condln<<<BS_, 192>>>(l);
        k_gemm_mma<<<dim3(QKV_N / BN, BS_ / BM), 256, GEMM_SMEM>>>(
            hhp, wqkvC + (size_t)l * QKV_N * 128, nullptr, nullptr, nullptr, qkvp,
            BS_, QKV_N, 128, D_, 3, 1);
        k_flash_tc<<<dim3(S_ / 128, B_ * H_), 256, FL_SMEM>>>();
        k_gemm_mma<<<dim3(D_ / BN, BS_ / BM), 256, GEMM_SMEM>>>(
            ohp, woT + (size_t)l * D_ * D_, bo + l * D_, xp, xp, nullptr,
            BS_, D_, D_, D_, 2, 0);
        k_condln<<<BS_, 192>>>(L_ + l);
        k_gemm_mma<<<dim3(4 * D_ / BN, BS_ / BM), 256, GEMM_SMEM>>>(
            hhp, w1T + (size_t)l * 4 * D_ * D_, b1 + l * 4 * D_, nullptr, nullptr, ffp,
            BS_, 4 * D_, D_, D_, 1, 0);
        k_gemm_mma<<<dim3(D_ / BN, BS_ / BM), 256, GEMM_SMEM>>>(
            ffp, w2T + (size_t)l * D_ * 4 * D_, b2 + l * D_, xp, xp, nullptr,
            BS_, D_, 4 * D_, 4 * D_, 2, 0);
    }
    k_condln<<<BS_, 192>>>(2 * L_);
    k_gemm_mma<<<dim3(V_ / BN, BS_ / BM), 256, GEMM_SMEM>>>(
        hhp, woutT, bout, nullptr, (float*)d_out, nullptr,
        BS_, V_, D_, D_, 0, 0);
}

// round 8
// speedup vs baseline: 14.2940x; 1.0097x over previous
#include <cuda_runtime.h>
#include <cuda_fp16.h>
#include <math.h>
#include <stdint.h>

// ---------------- constants ----------------
namespace {
constexpr int B_ = 8, S_ = 1024, D_ = 768, H_ = 12, DH_ = 64, V_ = 1024;
constexpr int L_ = 8;
constexpr int COND_ = 256, NACT_ = 4, DPA_ = 64;
constexpr int BS_ = B_ * S_;               // 8192
constexpr int QKV_N = 3 * D_;              // 2304
constexpr int NSLOT = 2 * L_ + 1;          // 17 cond-LN slots
// mma.sync GEMM tiling
constexpr int BM = 128, BN = 128;
constexpr int STAGE_BYTES = 32768;         // A 16KB + B 16KB per stage
constexpr int NST = 3;
constexpr int GEMM_SMEM = NST * STAGE_BYTES; // 96KB, 3-stage
// flash tiling
constexpr int FL_SMEM = 16384 + 2 * 16384; // Q 16KB + 2 stages of (K 8KB + V 8KB)
}

// ---------------- scratch (static device globals; no runtime alloc) ----------------
__device__ float  g_x  [BS_ * D_];
__device__ float  g_pe [S_ * D_];
__device__ __half g_hh [BS_ * D_];
__device__ __half g_qkv[BS_ * QKV_N];
__device__ __half g_oh [BS_ * D_];
__device__ __half g_ffh[BS_ * 4 * D_];
__device__ float  g_a  [B_ * COND_];
__device__ float  g_gvA[NSLOT * B_ * D_];
__device__ float  g_bvA[NSLOT * B_ * D_];
__device__ __half g_WqkvC[L_ * QKV_N * 128];   // compact block-diag, [N][128]
__device__ __half g_WoT  [L_ * D_ * D_];
__device__ __half g_W1T  [L_ * 4 * D_ * D_];
__device__ __half g_W2T  [L_ * D_ * 4 * D_];
__device__ __half g_WoutT[V_ * D_];

// ---------------- small helpers ----------------
__device__ __forceinline__ uint32_t smem_u32(const void* p) {
    uint32_t a;
    asm("{ .reg .u64 t; cvta.to.shared.u64 t, %1; cvt.u32.u64 %0, t; }" : "=r"(a) : "l"(p));
    return a;
}
__device__ __forceinline__ void cp16(uint32_t dst, const void* src) {
    asm volatile("cp.async.cg.shared.global [%0], [%1], 16;" :: "r"(dst), "l"(src) : "memory");
}
__device__ __forceinline__ void cp_commit() {
    asm volatile("cp.async.commit_group;" ::: "memory");
}
template <int N> __device__ __forceinline__ void cp_wait() {
    asm volatile("cp.async.wait_group %0;" :: "n"(N) : "memory");
}
__device__ __forceinline__ void ldm_x4(uint32_t* r, uint32_t addr) {
    asm volatile("ldmatrix.sync.aligned.m8n8.x4.shared.b16 {%0,%1,%2,%3}, [%4];"
                 : "=r"(r[0]), "=r"(r[1]), "=r"(r[2]), "=r"(r[3]) : "r"(addr));
}
__device__ __forceinline__ void ldm_x4_t(uint32_t* r, uint32_t addr) {
    asm volatile("ldmatrix.sync.aligned.m8n8.x4.trans.shared.b16 {%0,%1,%2,%3}, [%4];"
                 : "=r"(r[0]), "=r"(r[1]), "=r"(r[2]), "=r"(r[3]) : "r"(addr));
}
__device__ __forceinline__ void mma16816(float* c, const uint32_t* a, const uint32_t* b) {
    asm volatile("mma.sync.aligned.m16n8k16.row.col.f32.f16.f16.f32 "
                 "{%0,%1,%2,%3}, {%4,%5,%6,%7}, {%8,%9}, {%0,%1,%2,%3};"
                 : "+f"(c[0]), "+f"(c[1]), "+f"(c[2]), "+f"(c[3])
                 : "r"(a[0]), "r"(a[1]), "r"(a[2]), "r"(a[3]), "r"(b[0]), "r"(b[1]));
}
__device__ __forceinline__ uint32_t h2exp2_bits(__half2 x) {
    uint32_t y;
    asm("ex2.approx.f16x2 %0, %1;" : "=r"(y) : "r"(*(uint32_t*)&x));
    return y;
}
__device__ __forceinline__ float gelu_f(float x) {
    float x3 = x * x * x;
    return 0.5f * x * (1.f + tanhf(0.7978845608028654f * (x + 0.044715f * x3)));
}

// ---------------- batched weight transpose + fp16 convert: W[K,N] -> WT[N,K] ----------------
__global__ __launch_bounds__(256) void k_wt(const float* __restrict__ W,
                                            __half* __restrict__ WT, int K, int N) {
    __shared__ float tl[32][33];
    size_t off = (size_t)blockIdx.z * K * N;
    const float* Wp = W + off;
    __half* Tp = WT + off;
    int nb = blockIdx.x * 32, kb = blockIdx.y * 32;
    int tx = threadIdx.x & 31, ty = threadIdx.x >> 5;
    #pragma unroll
    for (int i = 0; i < 32; i += 8)
        tl[ty + i][tx] = Wp[(size_t)(kb + ty + i) * N + nb + tx];
    __syncthreads();
    #pragma unroll
    for (int i = 0; i < 32; i += 8)
        Tp[(size_t)(nb + ty + i) * K + kb + tx] = __float2half_rn(tl[tx][ty + i]);
}

// ---------------- compact block-diag QKV weight: [2304][128] per layer ----------------
__global__ __launch_bounds__(256) void k_wqkv(const float* __restrict__ Wq,
                                              const float* __restrict__ Wk,
                                              const float* __restrict__ Wv,
                                              __half* __restrict__ out) {
    int l = blockIdx.z;
    int i = blockIdx.x * 256 + threadIdx.x;
    if (i >= QKV_N * 128) return;
    int n = i >> 7, kp = i & 127;
    int part = n / D_, nn = n % D_;
    int h = nn >> 6, e = nn & 63;
    int hp = h & 1;
    const float* W = ((part == 0) ? Wq : (part == 1) ? Wk : Wv) + (size_t)l * H_ * DH_ * DH_;
    int d = kp - hp * 64;
    float v = (d >= 0 && d < 64) ? W[(size_t)(h * DH_ + d) * DH_ + e] : 0.f;
    out[(size_t)l * QKV_N * 128 + i] = __float2half_rn(v);
}

// ---------------- sinusoidal PE table ----------------
__global__ void k_pe() {
    int i = blockIdx.x * 256 + threadIdx.x;
    if (i >= S_ * D_) return;
    int s = i / D_, d = i % D_;
    int p2 = d & ~1;
    float freq = expf(-(float)p2 * (9.210340371976184f / (float)D_));
    float ang = (float)s * freq;
    g_pe[i] = (d & 1) ? cosf(ang) : sinf(ang);
}

// ---------------- embedding + PE ----------------
__global__ void k_embed(const int* __restrict__ tokens, const float* __restrict__ emb) {
    int row = blockIdx.x;
    int s = row & (S_ - 1);
    int tok = tokens[row];
    for (int d = threadIdx.x; d < D_; d += blockDim.x)
        g_x[row * D_ + d] = emb[tok * D_ + d] + g_pe[s * D_ + d];
}

// ---------------- action embedding gather ----------------
__global__ void k_act(const int* __restrict__ actions, const float* __restrict__ act_emb) {
    int i = blockIdx.x * blockDim.x + threadIdx.x;
    if (i >= B_ * COND_) return;
    int b = i / COND_, c = i % COND_;
    int n = c / DPA_, j = c % DPA_;
    g_a[i] = act_emb[actions[b * NACT_ + n] * DPA_ + j];
}

// ---------------- all conditional gain/shift vectors in one launch ----------------
__global__ __launch_bounds__(256) void k_condvec_all(const float* __restrict__ ln1_g,
                                                     const float* __restrict__ ln1_b,
                                                     const float* __restrict__ ln2_g,
                                                     const float* __restrict__ ln2_b,
                                                     const float* __restrict__ lnf_g,
                                                     const float* __restrict__ lnf_b) {
    int slot = blockIdx.y;
    const float *gw, *bw;
    if (slot < L_)            { size_t o = (size_t)slot * COND_ * D_;        gw = ln1_g + o; bw = ln1_b + o; }
    else if (slot < 2 * L_)   { size_t o = (size_t)(slot - L_) * COND_ * D_; gw = ln2_g + o; bw = ln2_b + o; }
    else                      { gw = lnf_g; bw = lnf_b; }
    int i = blockIdx.x * 256 + threadIdx.x;
    if (i >= B_ * D_) return;
    int b = i / D_, d = i % D_;
    const float* ar = g_a + b * COND_;
    float sg = 0.f, sb = 0.f;
    for (int c = 0; c < COND_; c++) {
        float av = ar[c];
        sg += av * gw[c * D_ + d];
        sb += av * bw[c * D_ + d];
    }
    g_gvA[(size_t)slot * B_ * D_ + i] = sg;
    g_bvA[(size_t)slot * B_ * D_ + i] = sb;
}

// ---------------- conditional layernorm (vectorized): g_x -> g_hh (fp16) ----------------
__global__ __launch_bounds__(192) void k_condln(int slot) {
    int row = blockIdx.x;
    int b = row >> 10;
    int t = threadIdx.x;
    const float4* xp = (const float4*)(g_x + (size_t)row * D_);
    float4 x = xp[t];
    float s1 = x.x + x.y + x.z + x.w;
    float s2 = x.x * x.x + x.y * x.y + x.z * x.z + x.w * x.w;
    #pragma unroll
    for (int o = 16; o; o >>= 1) {
        s1 += __shfl_xor_sync(0xffffffffu, s1, o);
        s2 += __shfl_xor_sync(0xffffffffu, s2, o);
    }
    __shared__ float rs1[6], rs2[6];
    __shared__ float mu_s, rstd_s;
    int w = t >> 5;
    if ((t & 31) == 0) { rs1[w] = s1; rs2[w] = s2; }
    __syncthreads();
    if (t == 0) {
        float a1 = 0.f, a2 = 0.f;
        #pragma unroll
        for (int i = 0; i < 6; i++) { a1 += rs1[i]; a2 += rs2[i]; }
        float mu = a1 / (float)D_;
        float var = a2 / (float)D_ - mu * mu;
        mu_s = mu;
        rstd_s = rsqrtf(var + 1e-5f);
    }
    __syncthreads();
    float mu = mu_s, rstd = rstd_s;
    const float4* gv = (const float4*)(g_gvA + (size_t)slot * B_ * D_ + b * D_);
    const float4* bv = (const float4*)(g_bvA + (size_t)slot * B_ * D_ + b * D_);
    float4 g = gv[t], bb = bv[t];
    float v0 = (x.x - mu) * rstd * g.x + bb.x;
    float v1 = (x.y - mu) * rstd * g.y + bb.y;
    float v2 = (x.z - mu) * rstd * g.z + bb.z;
    float v3 = (x.w - mu) * rstd * g.w + bb.w;
    uint2 pk;
    __half2 h01 = __floats2half2_rn(v0, v1);
    __half2 h23 = __floats2half2_rn(v2, v3);
    pk.x = *(uint32_t*)&h01;
    pk.y = *(uint32_t*)&h23;
    *(uint2*)(g_hh + (size_t)row * D_ + t * 4) = pk;
}

// ---------------- tensor-core flash attention (single-sync pipeline) ----------------
__global__ __launch_bounds__(256) void k_flash_tc() {
    extern __shared__ char fsm[];
    uint32_t sb = smem_u32(fsm);
    int t = threadIdx.x, lane = t & 31, wid = t >> 5;
    int bh = blockIdx.y;
    int b = bh / H_, h = bh % H_;
    int qBase = blockIdx.x * 128;
    int qr = lane >> 2, qc = lane & 3;

    const __half* qg = g_qkv + (size_t)(b * S_ + qBase) * QKV_N + h * DH_;
    #pragma unroll
    for (int i = 0; i < 4; i++) {
        int id = t + i * 256;
        int r = id >> 3, c8 = id & 7;
        cp16(sb + (uint32_t)(r * 128 + ((c8 ^ (r & 7)) << 4)), qg + (size_t)r * QKV_N + c8 * 8);
    }
    auto issueKV = [&](int kt, int s) {
        uint32_t st = sb + 16384u + (uint32_t)s * 16384u;
        const __half* kg = g_qkv + (size_t)(b * S_ + kt) * QKV_N + D_ + h * DH_;
        const __half* vg = kg + D_;
        #pragma unroll
        for (int i = 0; i < 2; i++) {
            int id = t + i * 256;
            int r = id >> 3, c8 = id & 7;
            cp16(st + (uint32_t)(r * 128 + ((c8 ^ (r & 7)) << 4)), kg + (size_t)r * QKV_N + c8 * 8);
        }
        #pragma unroll
        for (int i = 0; i < 2; i++) {
            int id = t + i * 256;
            int r = id >> 3, c8 = id & 7;
            cp16(st + 8192u + (uint32_t)(r * 128 + ((c8 ^ (r & 7)) << 4)), vg + (size_t)r * QKV_N + c8 * 8);
        }
        cp_commit();
    };
    issueKV(0, 0);

    uint32_t qa[4][4];
    float sfr[8][4];
    float o[8][4];
    #pragma unroll
    for (int j = 0; j < 8; j++)
        #pragma unroll
        for (int c = 0; c < 4; c++) o[j][c] = 0.f;
    float m_lo = -1e30f, m_hi = -1e30f, l_lo = 0.f, l_hi = 0.f;

    const int nT = S_ / 64;
    for (int tt = 0; tt < nT; tt++) {
        int st = tt & 1;
        cp_wait<0>();
        __syncthreads();                         // all warps done with buffer tt-1; data of tt visible
        if (tt + 1 < nT) issueKV((tt + 1) * 64, st ^ 1);   // safe: writes opposite buffer
        if (tt == 0) {
            const __half2 sc2 = __float2half2_rn(0.1803368801f);   // 0.125*log2(e)
            #pragma unroll
            for (int ks = 0; ks < 4; ks++) {
                int r = wid * 16 + (lane & 15);
                int chunk = ks * 2 + (lane >> 4);
                ldm_x4(qa[ks], sb + (uint32_t)(r * 128 + ((chunk ^ (r & 7)) << 4)));
                #pragma unroll
                for (int j = 0; j < 4; j++) {
                    __half2 hv = *(__half2*)&qa[ks][j];
                    hv = __hmul2(hv, sc2);
                    qa[ks][j] = *(uint32_t*)&hv;
                }
            }
        }
        uint32_t kBase = sb + 16384u + (uint32_t)st * 16384u;
        uint32_t vBase = kBase + 8192u;

        // ---- S = Qs @ K^T ----
        #pragma unroll
        for (int j = 0; j < 8; j++)
            #pragma unroll
            for (int c = 0; c < 4; c++) sfr[j][c] = 0.f;
        {
            int g2 = lane >> 3;
            int rowB = ((g2 >> 1) << 3) + (lane & 7);
            int kb = g2 & 1;
            #pragma unroll
            for (int ks = 0; ks < 4; ks++) {
                #pragma unroll
                for (int nh = 0; nh < 4; nh++) {
                    int r = nh * 16 + rowB;
                    int chunk = ks * 2 + kb;
                    uint32_t q4[4];
                    ldm_x4(q4, kBase + (uint32_t)(r * 128 + ((chunk ^ (r & 7)) << 4)));
                    uint32_t b0[2] = { q4[0], q4[1] };
                    uint32_t b1[2] = { q4[2], q4[3] };
                    mma16816(sfr[nh * 2],     qa[ks], b0);
                    mma16816(sfr[nh * 2 + 1], qa[ks], b1);
                }
            }
        }
        // ---- row maxes + rescale O ----
        float tl = sfr[0][0], th = sfr[0][2];
        #pragma unroll
        for (int j = 0; j < 8; j++) {
            tl = fmaxf(tl, fmaxf(sfr[j][0], sfr[j][1]));
            th = fmaxf(th, fmaxf(sfr[j][2], sfr[j][3]));
        }
        tl = fmaxf(tl, __shfl_xor_sync(0xffffffffu, tl, 1));
        tl = fmaxf(tl, __shfl_xor_sync(0xffffffffu, tl, 2));
        th = fmaxf(th, __shfl_xor_sync(0xffffffffu, th, 1));
        th = fmaxf(th, __shfl_xor_sync(0xffffffffu, th, 2));
        float mn_lo = fmaxf(m_lo, tl), mn_hi = fmaxf(m_hi, th);
        float corr_lo = exp2f(m_lo - mn_lo), corr_hi = exp2f(m_hi - mn_hi);
        l_lo *= corr_lo; l_hi *= corr_hi;
        m_lo = mn_lo; m_hi = mn_hi;
        #pragma unroll
        for (int j = 0; j < 8; j++) {
            o[j][0] *= corr_lo; o[j][1] *= corr_lo;
            o[j][2] *= corr_hi; o[j][3] *= corr_hi;
        }
        // ---- exp + PV, interleaved per k-chunk ----
        float ps_lo = 0.f, ps_hi = 0.f;
        #pragma unroll
        for (int ks = 0; ks < 4; ks++) {
            uint32_t pa[4];
            #pragma unroll
            for (int jj = 0; jj < 2; jj++) {
                int j = 2 * ks + jj;
                __half2 e0h = __floats2half2_rn(sfr[j][0] - mn_lo, sfr[j][1] - mn_lo);
                __half2 e1h = __floats2half2_rn(sfr[j][2] - mn_hi, sfr[j][3] - mn_hi);
                uint32_t p0 = h2exp2_bits(e0h);
                uint32_t p1 = h2exp2_bits(e1h);
                pa[2 * jj] = p0; pa[2 * jj + 1] = p1;
                float2 f0 = __half22float2(*(__half2*)&p0);
                float2 f1 = __half22float2(*(__half2*)&p1);
                ps_lo += f0.x + f0.y;
                ps_hi += f1.x + f1.y;
            }
            #pragma unroll
            for (int jp = 0; jp < 4; jp++) {
                int r = ks * 16 + (lane & 15);
                int chunk = jp * 2 + (lane >> 4);
                uint32_t q4[4];
                ldm_x4_t(q4, vBase + (uint32_t)(r * 128 + ((chunk ^ (r & 7)) << 4)));
                uint32_t b0[2] = { q4[0], q4[1] };
                uint32_t b1[2] = { q4[2], q4[3] };
                mma16816(o[2 * jp],     pa, b0);
                mma16816(o[2 * jp + 1], pa, b1);
            }
        }
        l_lo += ps_lo;
        l_hi += ps_hi;
        // no trailing sync — top-of-loop sync covers the buffer hazard
    }
    l_lo += __shfl_xor_sync(0xffffffffu, l_lo, 1);
    l_lo += __shfl_xor_sync(0xffffffffu, l_lo, 2);
    l_hi += __shfl_xor_sync(0xffffffffu, l_hi, 1);
    l_hi += __shfl_xor_sync(0xffffffffu, l_hi, 2);
    float inv_lo = 1.f / l_lo, inv_hi = 1.f / l_hi;
    int rlo = b * S_ + qBase + wid * 16 + qr;
    #pragma unroll
    for (int j = 0; j < 8; j++) {
        int col = h * DH_ + j * 8 + qc * 2;
        *(__half2*)(g_oh + (size_t)rlo * D_ + col) =
            __floats2half2_rn(o[j][0] * inv_lo, o[j][1] * inv_lo);
        *(__half2*)(g_oh + (size_t)(rlo + 8) * D_ + col) =
            __floats2half2_rn(o[j][2] * inv_hi, o[j][3] * inv_hi);
    }
}

// ---------------- fp16 mma.sync GEMM, 3-stage single-sync pipeline ----------------
__global__ __launch_bounds__(256) void k_gemm_mma(const __half* __restrict__ A,
                                                  const __half* __restrict__ Bt,
                                                  const float* __restrict__ bias,
                                                  const float* __restrict__ res,
                                                  float* __restrict__ Cf,
                                                  __half* __restrict__ Ch,
                                                  int M, int N, int K, int lda,
                                                  int epi, int qkvMode) {
    extern __shared__ char smem[];
    uint32_t sb = smem_u32(smem);
    int t = threadIdx.x;
    int lane = t & 31, wid = t >> 5;
    int warpM = wid >> 2, warpN = wid & 3;
    int rowBase = blockIdx.y * BM, colBase = blockIdx.x * BN;
    int kOff = qkvMode ? (colBase % D_) : 0;
    const __half* Ag = A + (size_t)rowBase * lda + kOff;
    const __half* Bg = Bt + (size_t)colBase * K;
    const int nCh = K >> 6;

    float acc[4][4][4];
    #pragma unroll
    for (int i = 0; i < 4; i++)
        #pragma unroll
        for (int j = 0; j < 4; j++)
            #pragma unroll
            for (int c = 0; c < 4; c++) acc[i][j][c] = 0.f;

    auto issue = [&](int ch) {
        uint32_t stage = sb + (uint32_t)(ch % NST) * STAGE_BYTES;
        int kt = ch << 6;
        #pragma unroll
        for (int i = 0; i < 4; i++) {
            int id = t + i * 256;
            int r = id >> 3, c = id & 7;
            cp16(stage + (uint32_t)(r * 128 + ((c ^ (r & 7)) << 4)), Ag + (size_t)r * lda + kt + c * 8);
        }
        #pragma unroll
        for (int i = 0; i < 4; i++) {
            int id = t + i * 256;
            int r = id >> 3, c = id & 7;
            cp16(stage + 16384u + (uint32_t)(r * 128 + ((c ^ (r & 7)) << 4)), Bg + (size_t)r * K + kt + c * 8);
        }
        cp_commit();
    };

    issue(0);
    if (nCh > 1) issue(1);
    for (int ch = 0; ch < nCh; ch++) {
        if (ch + 1 < nCh) cp_wait<1>();
        else              cp_wait<0>();
        __syncthreads();                       // buffer ch visible; all warps done with buffer ch-1
        if (ch + 2 < nCh) issue(ch + 2);       // writes buffer (ch-1)%3 — safe after the sync

        uint32_t aBase = sb + (uint32_t)(ch % NST) * STAGE_BYTES;
        uint32_t bBase = aBase + 16384u;
        int lrA = lane & 15, kbA = lane >> 4;
        int g2 = lane >> 3;
        int rowOffB = ((g2 >> 1) << 3) + (lane & 7);
        int kbB = g2 & 1;
        #pragma unroll
        for (int ks = 0; ks < 4; ks++) {
            uint32_t af[4][4];
            int chunkA = ks * 2 + kbA;
            #pragma unroll
            for (int mi = 0; mi < 4; mi++) {
                int r = warpM * 64 + mi * 16 + lrA;
                ldm_x4(af[mi], aBase + (uint32_t)(r * 128 + ((chunkA ^ (r & 7)) << 4)));
            }
            uint32_t bf[4][2];
            int chunkB = ks * 2 + kbB;
            #pragma unroll
            for (int nh = 0; nh < 2; nh++) {
                int r = warpN * 32 + nh * 16 + rowOffB;
                uint32_t q[4];
                ldm_x4(q, bBase + (uint32_t)(r * 128 + ((chunkB ^ (r & 7)) << 4)));
                bf[nh * 2][0] = q[0];     bf[nh * 2][1] = q[1];
                bf[nh * 2 + 1][0] = q[2]; bf[nh * 2 + 1][1] = q[3];
            }
            #pragma unroll
            for (int mi = 0; mi < 4; mi++)
                #pragma unroll
                for (int ni = 0; ni < 4; ni++)
                    mma16816(acc[mi][ni], af[mi], bf[ni]);
        }
        // no trailing sync
    }

    int qr = lane >> 2, qc = lane & 3;
    #pragma unroll
    for (int mi = 0; mi < 4; mi++) {
        #pragma unroll
        for (int ni = 0; ni < 4; ni++) {
            int row0 = rowBase + warpM * 64 + mi * 16 + qr;
            int col  = colBase + warpN * 32 + ni * 8 + qc * 2;
            #pragma unroll
            for (int hrow = 0; hrow < 2; hrow++) {
                int rr = row0 + hrow * 8;
                float v0 = acc[mi][ni][hrow * 2];
                float v1 = acc[mi][ni][hrow * 2 + 1];
                if (epi == 0 || epi == 2) {
                    v0 += bias[col]; v1 += bias[col + 1];
                    if (epi == 2) {
                        const float* rp = res + (size_t)rr * N + col;
                        v0 += rp[0]; v1 += rp[1];
                    }
                    float2 ov; ov.x = v0; ov.y = v1;
                    *(float2*)(Cf + (size_t)rr * N + col) = ov;
                } else if (epi == 1) {
                    v0 = gelu_f(v0 + bias[col]);
                    v1 = gelu_f(v1 + bias[col + 1]);
                    *(__half2*)(Ch + (size_t)rr * N + col) = __floats2half2_rn(v0, v1);
                } else {
                    *(__half2*)(Ch + (size_t)rr * N + col) = __floats2half2_rn(v0, v1);
                }
            }
        }
    }
}

// ---------------- launch sequence ----------------
extern "C" void kernel_launch(void* const* d_in, const int* in_sizes, int n_in,
                              void* d_out, int out_size) {
    const int*   tokens  = (const int*)d_in[0];
    const int*   actions = (const int*)d_in[1];
    const float* emb     = (const float*)d_in[2];
    const float* act_emb = (const float*)d_in[3];
    const float* ln1_g   = (const float*)d_in[4];
    const float* ln1_b   = (const float*)d_in[5];
    const float* Wq      = (const float*)d_in[6];
    const float* Wk      = (const float*)d_in[7];
    const float* Wv      = (const float*)d_in[8];
    const float* Wo      = (const float*)d_in[9];
    const float* bo      = (const float*)d_in[10];
    const float* ln2_g   = (const float*)d_in[11];
    const float* ln2_b   = (const float*)d_in[12];
    const float* W1      = (const float*)d_in[13];
    const float* b1      = (const float*)d_in[14];
    const float* W2      = (const float*)d_in[15];
    const float* b2      = (const float*)d_in[16];
    const float* lnf_g   = (const float*)d_in[17];
    const float* lnf_b   = (const float*)d_in[18];
    const float* Wout    = (const float*)d_in[19];
    const float* bout    = (const float*)d_in[20];

    float *xp;
    __half *hhp, *qkvp, *ohp, *ffp, *wqkvC, *woT, *w1T, *w2T, *woutT;
    cudaGetSymbolAddress((void**)&xp,    g_x);
    cudaGetSymbolAddress((void**)&hhp,   g_hh);
    cudaGetSymbolAddress((void**)&qkvp,  g_qkv);
    cudaGetSymbolAddress((void**)&ohp,   g_oh);
    cudaGetSymbolAddress((void**)&ffp,   g_ffh);
    cudaGetSymbolAddress((void**)&wqkvC, g_WqkvC);
    cudaGetSymbolAddress((void**)&woT,   g_WoT);
    cudaGetSymbolAddress((void**)&w1T,   g_W1T);
    cudaGetSymbolAddress((void**)&w2T,   g_W2T);
    cudaGetSymbolAddress((void**)&woutT, g_WoutT);

    cudaFuncSetAttribute(k_flash_tc, cudaFuncAttributeMaxDynamicSharedMemorySize, FL_SMEM);
    cudaFuncSetAttribute(k_gemm_mma, cudaFuncAttributeMaxDynamicSharedMemorySize, GEMM_SMEM);

    // ---- prep phase (batched) ----
    k_wt<<<dim3(D_ / 32, D_ / 32, L_), 256>>>(Wo, woT, D_, D_);
    k_wt<<<dim3(4 * D_ / 32, D_ / 32, L_), 256>>>(W1, w1T, D_, 4 * D_);
    k_wt<<<dim3(D_ / 32, 4 * D_ / 32, L_), 256>>>(W2, w2T, 4 * D_, D_);
    k_wt<<<dim3(V_ / 32, D_ / 32, 1), 256>>>(Wout, woutT, D_, V_);
    k_wqkv<<<dim3((QKV_N * 128 + 255) / 256, 1, L_), 256>>>(Wq, Wk, Wv, wqkvC);
    k_pe<<<(S_ * D_ + 255) / 256, 256>>>();
    k_embed<<<BS_, 256>>>(tokens, emb);
    k_act<<<(B_ * COND_ + 255) / 256, 256>>>(actions, act_emb);
    k_condvec_all<<<dim3((B_ * D_ + 255) / 256, NSLOT), 256>>>(ln1_g, ln1_b, ln2_g, ln2_b, lnf_g, lnf_b);

    // ---- layers ----
    for (int l = 0; l < L_; l++) {
        k_condln<<<BS_, 192>>>(l);
        k_gemm_mma<<<dim3(QKV_N / BN, BS_ / BM), 256, GEMM_SMEM>>>(
            hhp, wqkvC + (size_t)l * QKV_N * 128, nullptr, nullptr, nullptr, qkvp,
            BS_, QKV_N, 128, D_, 3, 1);
        k_flash_tc<<<dim3(S_ / 128, B_ * H_), 256, FL_SMEM>>>();
        k_gemm_mma<<<dim3(D_ / BN, BS_ / BM), 256, GEMM_SMEM>>>(
            ohp, woT + (size_t)l * D_ * D_, bo + l * D_, xp, xp, nullptr,
            BS_, D_, D_, D_, 2, 0);
        k_condln<<<BS_, 192>>>(L_ + l);
        k_gemm_mma<<<dim3(4 * D_ / BN, BS_ / BM), 256, GEMM_SMEM>>>(
            hhp, w1T + (size_t)l * 4 * D_ * D_, b1 + l * 4 * D_, nullptr, nullptr, ffp,
            BS_, 4 * D_, D_, D_, 1, 0);
        k_gemm_mma<<<dim3(D_ / BN, BS_ / BM), 256, GEMM_SMEM>>>(
            ffp, w2T + (size_t)l * D_ * 4 * D_, b2 + l * D_, xp, xp, nullptr,
            BS_, D_, 4 * D_, 4 * D_, 2, 0);
    }
    k_condln<<<BS_, 192>>>(2 * L_);
    k_gemm_mma<<<dim3(V_ / BN, BS_ / BM), 256, GEMM_SMEM>>>(
        hhp, woutT, bout, nullptr, (float*)d_out, nullptr,
        BS_, V_, D_, D_, 0, 0);
}